// round 3
// baseline (speedup 1.0000x reference)
#include <cuda_runtime.h>
#include <cstdint>
#include <math.h>

// Problem constants
#define B_     64
#define NPTS_  1024
#define DIM_   256
#define BOOK_  2048
#define NC_    16
#define ROWS_  65536            // B_*NPTS_

// Output layout: concat(zq[64,1024,256], precision_q[1], logits[64,1024,2048], mu_mix[64,1024,256])
#define ZQ_OFF   ((size_t)0)
#define PREC_OFF ((size_t)16777216)
#define LOG_OFF  ((size_t)16777217)
#define MU_OFF   ((size_t)150994945)

// Scratch (allocation-free rule: __device__ globals)
__device__ float g_zp[(size_t)ROWS_ * DIM_];   // 64 MB: z + mu_mix
__device__ float g_zpsq[ROWS_];                // row squared norms
__device__ float g_booksq[BOOK_];              // book squared norms

// ---------------------------------------------------------------------------
// Kernel 1: mu_mix = c_probs @ mu ; zp = z + mu_mix ; row norms
// one block per (b,n) row, 64 threads, float4 per thread
// ---------------------------------------------------------------------------
__global__ __launch_bounds__(64) void prep_kernel(
    const float* __restrict__ z, const float* __restrict__ c_probs,
    const float* __restrict__ mu, float* __restrict__ out)
{
    __shared__ float cp[NC_];
    __shared__ float red[2];
    int r = blockIdx.x;
    int b = r >> 10, n = r & 1023;
    int t = threadIdx.x;
    if (t < NC_) cp[t] = c_probs[b * NC_ + t];
    __syncthreads();

    const float4* z4 = reinterpret_cast<const float4*>(z) + (size_t)r * 64;
    float4 zv = z4[t];
    float4 m = make_float4(0.f, 0.f, 0.f, 0.f);
#pragma unroll
    for (int c = 0; c < NC_; c++) {
        const float4* mu4 = reinterpret_cast<const float4*>(mu) + ((size_t)c * NPTS_ + n) * 64;
        float4 mv = mu4[t];
        float w = cp[c];
        m.x = fmaf(w, mv.x, m.x); m.y = fmaf(w, mv.y, m.y);
        m.z = fmaf(w, mv.z, m.z); m.w = fmaf(w, mv.w, m.w);
    }
    // mu_mix output region is misaligned (odd float offset) -> scalar stores
    float* om = out + MU_OFF + (size_t)r * DIM_ + t * 4;
    om[0] = m.x; om[1] = m.y; om[2] = m.z; om[3] = m.w;

    float4 zp = make_float4(zv.x + m.x, zv.y + m.y, zv.z + m.z, zv.w + m.w);
    reinterpret_cast<float4*>(g_zp)[(size_t)r * 64 + t] = zp;

    float ss = zp.x*zp.x + zp.y*zp.y + zp.z*zp.z + zp.w*zp.w;
#pragma unroll
    for (int o = 16; o; o >>= 1) ss += __shfl_xor_sync(0xffffffffu, ss, o);
    if ((t & 31) == 0) red[t >> 5] = ss;
    __syncthreads();
    if (t == 0) g_zpsq[r] = red[0] + red[1];
}

// ---------------------------------------------------------------------------
// Kernel 2: book row norms + precision_q output
// ---------------------------------------------------------------------------
__global__ __launch_bounds__(64) void booksq_kernel(
    const float* __restrict__ book, const float* __restrict__ lpq,
    float* __restrict__ out)
{
    __shared__ float red[2];
    int r = blockIdx.x, t = threadIdx.x;
    const float4* b4 = reinterpret_cast<const float4*>(book) + (size_t)r * 64;
    float4 v = b4[t];
    float ss = v.x*v.x + v.y*v.y + v.z*v.z + v.w*v.w;
#pragma unroll
    for (int o = 16; o; o >>= 1) ss += __shfl_xor_sync(0xffffffffu, ss, o);
    if ((t & 31) == 0) red[t >> 5] = ss;
    __syncthreads();
    if (t == 0) g_booksq[r] = red[0] + red[1];
    if (r == 0 && t == 0) {
        float pq = expf(lpq[0]);
        out[PREC_OFF] = 0.5f / fmaxf(pq, 1e-10f);
    }
}

// ---------------------------------------------------------------------------
// Kernel 3: logits GEMM. C[65536,2048]; 128x128 CTA tile, BK=16, 8x8 per thread,
// double-buffered smem (32 KB static). logits = -(zsq + bsq - 2*dot)*prec
// ---------------------------------------------------------------------------
#define BM 128
#define BN 128
#define BKc 16

__global__ __launch_bounds__(256, 2) void logits_kernel(
    const float* __restrict__ book, const float* __restrict__ lpq,
    float* __restrict__ out)
{
    __shared__ float As[2][BKc][BM];
    __shared__ float Bs[2][BKc][BN];
    int tid = threadIdx.x;
    int tx = tid & 15, ty = tid >> 4;
    int rowBase = blockIdx.y * BM;
    int colBase = blockIdx.x * BN;

    float acc[8][8];
#pragma unroll
    for (int i = 0; i < 8; i++)
#pragma unroll
        for (int j = 0; j < 8; j++) acc[i][j] = 0.f;

    auto stage = [&](int kc, int buf) {
#pragma unroll
        for (int i = 0; i < 2; i++) {
            int f  = tid + i * 256;
            int rr = f >> 2;          // 0..127
            int kq = (f & 3) * 4;     // 0,4,8,12
            float4 a = *reinterpret_cast<const float4*>(
                g_zp + (size_t)(rowBase + rr) * DIM_ + kc + kq);
            As[buf][kq + 0][rr] = a.x; As[buf][kq + 1][rr] = a.y;
            As[buf][kq + 2][rr] = a.z; As[buf][kq + 3][rr] = a.w;
            float4 bv = *reinterpret_cast<const float4*>(
                book + (size_t)(colBase + rr) * DIM_ + kc + kq);
            Bs[buf][kq + 0][rr] = bv.x; Bs[buf][kq + 1][rr] = bv.y;
            Bs[buf][kq + 2][rr] = bv.z; Bs[buf][kq + 3][rr] = bv.w;
        }
    };

    stage(0, 0);
    __syncthreads();
    int buf = 0;
    for (int kc = 0; kc < DIM_; kc += BKc) {
        if (kc + BKc < DIM_) stage(kc + BKc, buf ^ 1);
#pragma unroll
        for (int k = 0; k < BKc; k++) {
            float a[8], bb[8];
            *reinterpret_cast<float4*>(&a[0]) = *reinterpret_cast<const float4*>(&As[buf][k][ty * 8]);
            *reinterpret_cast<float4*>(&a[4]) = *reinterpret_cast<const float4*>(&As[buf][k][ty * 8 + 4]);
            *reinterpret_cast<float4*>(&bb[0]) = *reinterpret_cast<const float4*>(&Bs[buf][k][tx * 8]);
            *reinterpret_cast<float4*>(&bb[4]) = *reinterpret_cast<const float4*>(&Bs[buf][k][tx * 8 + 4]);
#pragma unroll
            for (int i = 0; i < 8; i++)
#pragma unroll
                for (int j = 0; j < 8; j++)
                    acc[i][j] = fmaf(a[i], bb[j], acc[i][j]);
        }
        __syncthreads();
        buf ^= 1;
    }

    float prec = 0.5f / fmaxf(expf(lpq[0]), 1e-10f);
    float zr[8], bq[8];
#pragma unroll
    for (int i = 0; i < 8; i++) zr[i] = g_zpsq[rowBase + ty * 8 + i];
#pragma unroll
    for (int j = 0; j < 8; j++) bq[j] = g_booksq[colBase + tx * 8 + j];
#pragma unroll
    for (int i = 0; i < 8; i++) {
        size_t base = LOG_OFF + (size_t)(rowBase + ty * 8 + i) * BOOK_ + colBase + tx * 8;
#pragma unroll
        for (int j = 0; j < 8; j++) {
            float dist = zr[i] + bq[j] - 2.0f * acc[i][j];
            out[base + j] = -dist * prec;
        }
    }
}

// ---------------------------------------------------------------------------
// JAX threefry2x32-20 with key (0, 42), matching jax.random.key(42).
// PARTITIONABLE path (JAX >= 0.5 default): counter is 64-bit index split as
// (hi, lo) = (idx>>32, idx) = (0, idx) here; 32-bit bits = out.x ^ out.y.
// ---------------------------------------------------------------------------
__device__ __forceinline__ uint32_t threefry_bits_0_42(uint32_t idx)
{
    const uint32_t ks0 = 0u, ks1 = 42u, ks2 = 0x1BD11BDAu ^ 42u;
    uint32_t x0 = 0u, x1 = idx;
    x0 += ks0; x1 += ks1;
#define TFR(r) { x0 += x1; x1 = (x1 << (r)) | (x1 >> (32 - (r))); x1 ^= x0; }
    TFR(13) TFR(15) TFR(26) TFR(6)
    x0 += ks1; x1 += ks2 + 1u;
    TFR(17) TFR(29) TFR(16) TFR(24)
    x0 += ks2; x1 += ks0 + 2u;
    TFR(13) TFR(15) TFR(26) TFR(6)
    x0 += ks0; x1 += ks1 + 3u;
    TFR(17) TFR(29) TFR(16) TFR(24)
    x0 += ks1; x1 += ks2 + 4u;
    TFR(13) TFR(15) TFR(26) TFR(6)
    x0 += ks2; x1 += ks0 + 5u;
#undef TFR
    return x0 ^ x1;
}

// ---------------------------------------------------------------------------
// Kernel 4: gumbel + exact softmax (16 rows in 128 KB smem) + zq = enc @ book
// ---------------------------------------------------------------------------
#define TMR 16

__global__ __launch_bounds__(256, 1) void softmax_zq_kernel(
    const float* __restrict__ book, const void* __restrict__ temp_ptr,
    float* __restrict__ out)
{
    extern __shared__ float Ps[];                 // TMR * 2048
    __shared__ float redbuf[8 * TMR];
    __shared__ float rowmax[TMR];
    __shared__ float rowsum[TMR];
    int tid = threadIdx.x;
    int lane = tid & 31, warp = tid >> 5;
    uint32_t r0 = blockIdx.x * TMR;

    // temperature may arrive as int32 or float32; disambiguate by plausibility
    float tval;
    {
        float f = *reinterpret_cast<const float*>(temp_ptr);
        int  iv = *reinterpret_cast<const int*>(temp_ptr);
        tval = (f >= 0.015625f && f <= 64.0f) ? f : (float)iv;
    }
    float invT = 1.0f / tval;

    const float* lg = out + LOG_OFF;

    // Phase 1: logits + gumbel into smem, per-thread row maxes
    float pm[TMR];
#pragma unroll
    for (int rr = 0; rr < TMR; rr++) {
        uint32_t row = r0 + rr;
        float m = -3.4e38f;
#pragma unroll
        for (int j = 0; j < 8; j++) {
            uint32_t col = j * 256 + tid;
            uint32_t idx = row * 2048u + col;
            float l = lg[idx];
            uint32_t bits = threefry_bits_0_42(idx);
            float u = __uint_as_float((bits >> 9) | 0x3f800000u) - 1.0f;
            float g = -logf(-logf(u + 1e-10f) + 1e-10f);
            float v = (l + g) * invT;
            Ps[rr * 2048 + col] = v;
            m = fmaxf(m, v);
        }
        pm[rr] = m;
    }
#pragma unroll
    for (int rr = 0; rr < TMR; rr++) {
        float m = pm[rr];
#pragma unroll
        for (int o = 16; o; o >>= 1) m = fmaxf(m, __shfl_xor_sync(0xffffffffu, m, o));
        if (lane == 0) redbuf[warp * TMR + rr] = m;
    }
    __syncthreads();
    if (tid < TMR) {
        float m = redbuf[tid];
#pragma unroll
        for (int w = 1; w < 8; w++) m = fmaxf(m, redbuf[w * TMR + tid]);
        rowmax[tid] = m;
    }
    __syncthreads();

    // Phase 2: exp(x - max), per-row sums
    float psacc[TMR];
#pragma unroll
    for (int rr = 0; rr < TMR; rr++) {
        float m = rowmax[rr];
        float s = 0.f;
#pragma unroll
        for (int j = 0; j < 8; j++) {
            int id = rr * 2048 + j * 256 + tid;
            float e = __expf(Ps[id] - m);
            Ps[id] = e;
            s += e;
        }
        psacc[rr] = s;
    }
#pragma unroll
    for (int rr = 0; rr < TMR; rr++) {
        float s = psacc[rr];
#pragma unroll
        for (int o = 16; o; o >>= 1) s += __shfl_xor_sync(0xffffffffu, s, o);
        if (lane == 0) redbuf[warp * TMR + rr] = s;
    }
    __syncthreads();
    if (tid < TMR) {
        float s = redbuf[tid];
#pragma unroll
        for (int w = 1; w < 8; w++) s += redbuf[w * TMR + tid];
        rowsum[tid] = s;
    }
    __syncthreads();

    // Phase 3: acc[rr] = sum_k Ps[rr][k] * book[k][tid]   (smem LDS are broadcasts)
    float acc[TMR];
#pragma unroll
    for (int rr = 0; rr < TMR; rr++) acc[rr] = 0.f;
    const float* bcol = book + tid;
#pragma unroll 2
    for (int k = 0; k < 2048; k += 4) {
        float b0 = bcol[(k + 0) * 256];
        float b1 = bcol[(k + 1) * 256];
        float b2 = bcol[(k + 2) * 256];
        float b3 = bcol[(k + 3) * 256];
#pragma unroll
        for (int rr = 0; rr < TMR; rr++) {
            float4 p = *reinterpret_cast<const float4*>(&Ps[rr * 2048 + k]);
            float a = acc[rr];
            a = fmaf(p.x, b0, a); a = fmaf(p.y, b1, a);
            a = fmaf(p.z, b2, a); a = fmaf(p.w, b3, a);
            acc[rr] = a;
        }
    }
#pragma unroll
    for (int rr = 0; rr < TMR; rr++) {
        out[ZQ_OFF + (size_t)(r0 + rr) * DIM_ + tid] = acc[rr] / rowsum[rr];
    }
}

// ---------------------------------------------------------------------------
extern "C" void kernel_launch(void* const* d_in, const int* in_sizes, int n_in,
                              void* d_out, int out_size)
{
    const float* z       = (const float*)d_in[0];
    const float* c_probs = (const float*)d_in[1];
    const float* lpq     = (const float*)d_in[2];
    const float* book    = (const float*)d_in[3];
    const float* mu      = (const float*)d_in[4];
    const void*  temp    = d_in[5];
    float* out = (float*)d_out;

    cudaFuncSetAttribute(softmax_zq_kernel,
                         cudaFuncAttributeMaxDynamicSharedMemorySize,
                         TMR * 2048 * (int)sizeof(float));

    prep_kernel<<<ROWS_, 64>>>(z, c_probs, mu, out);
    booksq_kernel<<<BOOK_, 64>>>(book, lpq, out);
    logits_kernel<<<dim3(BOOK_ / BN, ROWS_ / BM), 256>>>(book, lpq, out);
    softmax_zq_kernel<<<ROWS_ / TMR, 256, TMR * 2048 * (int)sizeof(float)>>>(book, temp, out);
}

// round 6
// speedup vs baseline: 1.1453x; 1.1453x over previous
#include <cuda_runtime.h>
#include <cstdint>
#include <math.h>

// Problem constants
#define B_     64
#define NPTS_  1024
#define DIM_   256
#define BOOK_  2048
#define NC_    16
#define ROWS_  65536            // B_*NPTS_

// Output layout: concat(zq[64,1024,256], precision_q[1], logits[64,1024,2048], mu_mix[64,1024,256])
#define ZQ_OFF   ((size_t)0)
#define PREC_OFF ((size_t)16777216)
#define LOG_OFF  ((size_t)16777217)
#define MU_OFF   ((size_t)150994945)

// Scratch (allocation-free rule: __device__ globals)
__device__ float g_zp[(size_t)ROWS_ * DIM_];   // 64 MB: z + mu_mix
__device__ float g_zpsq[ROWS_];                // row squared norms
__device__ float g_booksq[BOOK_];              // book squared norms

// ---------------------------------------------------------------------------
// Kernel 1: mu_mix = c_probs @ mu ; zp = z + mu_mix ; row norms
// ---------------------------------------------------------------------------
__global__ __launch_bounds__(64) void prep_kernel(
    const float* __restrict__ z, const float* __restrict__ c_probs,
    const float* __restrict__ mu, float* __restrict__ out)
{
    __shared__ float cp[NC_];
    __shared__ float red[2];
    int r = blockIdx.x;
    int b = r >> 10, n = r & 1023;
    int t = threadIdx.x;
    if (t < NC_) cp[t] = c_probs[b * NC_ + t];
    __syncthreads();

    const float4* z4 = reinterpret_cast<const float4*>(z) + (size_t)r * 64;
    float4 zv = z4[t];
    float4 m = make_float4(0.f, 0.f, 0.f, 0.f);
#pragma unroll
    for (int c = 0; c < NC_; c++) {
        const float4* mu4 = reinterpret_cast<const float4*>(mu) + ((size_t)c * NPTS_ + n) * 64;
        float4 mv = mu4[t];
        float w = cp[c];
        m.x = fmaf(w, mv.x, m.x); m.y = fmaf(w, mv.y, m.y);
        m.z = fmaf(w, mv.z, m.z); m.w = fmaf(w, mv.w, m.w);
    }
    float* om = out + MU_OFF + (size_t)r * DIM_ + t * 4;
    om[0] = m.x; om[1] = m.y; om[2] = m.z; om[3] = m.w;

    float4 zp = make_float4(zv.x + m.x, zv.y + m.y, zv.z + m.z, zv.w + m.w);
    reinterpret_cast<float4*>(g_zp)[(size_t)r * 64 + t] = zp;

    float ss = zp.x*zp.x + zp.y*zp.y + zp.z*zp.z + zp.w*zp.w;
#pragma unroll
    for (int o = 16; o; o >>= 1) ss += __shfl_xor_sync(0xffffffffu, ss, o);
    if ((t & 31) == 0) red[t >> 5] = ss;
    __syncthreads();
    if (t == 0) g_zpsq[r] = red[0] + red[1];
}

// ---------------------------------------------------------------------------
// Kernel 2: book row norms + precision_q output
// ---------------------------------------------------------------------------
__global__ __launch_bounds__(64) void booksq_kernel(
    const float* __restrict__ book, const float* __restrict__ lpq,
    float* __restrict__ out)
{
    __shared__ float red[2];
    int r = blockIdx.x, t = threadIdx.x;
    const float4* b4 = reinterpret_cast<const float4*>(book) + (size_t)r * 64;
    float4 v = b4[t];
    float ss = v.x*v.x + v.y*v.y + v.z*v.z + v.w*v.w;
#pragma unroll
    for (int o = 16; o; o >>= 1) ss += __shfl_xor_sync(0xffffffffu, ss, o);
    if ((t & 31) == 0) red[t >> 5] = ss;
    __syncthreads();
    if (t == 0) g_booksq[r] = red[0] + red[1];
    if (r == 0 && t == 0) {
        float pq = expf(lpq[0]);
        out[PREC_OFF] = 0.5f / fmaxf(pq, 1e-10f);
    }
}

// ---------------------------------------------------------------------------
// JAX threefry2x32-20, key (0,42), partitionable path: bits = out.x ^ out.y
// ---------------------------------------------------------------------------
__device__ __noinline__ uint32_t threefry_bits_0_42(uint32_t idx)
{
    const uint32_t ks0 = 0u, ks1 = 42u, ks2 = 0x1BD11BDAu ^ 42u;
    uint32_t x0 = 0u, x1 = idx;
    x0 += ks0; x1 += ks1;
#define TFR(r) { x0 += x1; x1 = (x1 << (r)) | (x1 >> (32 - (r))); x1 ^= x0; }
    TFR(13) TFR(15) TFR(26) TFR(6)
    x0 += ks1; x1 += ks2 + 1u;
    TFR(17) TFR(29) TFR(16) TFR(24)
    x0 += ks2; x1 += ks0 + 2u;
    TFR(13) TFR(15) TFR(26) TFR(6)
    x0 += ks0; x1 += ks1 + 3u;
    TFR(17) TFR(29) TFR(16) TFR(24)
    x0 += ks1; x1 += ks2 + 4u;
    TFR(13) TFR(15) TFR(26) TFR(6)
    x0 += ks2; x1 += ks0 + 5u;
#undef TFR
    return x0 ^ x1;
}

// ---------------------------------------------------------------------------
// Fused kernel: per CTA = 16 rows. For each 512-col chunk:
//   GEMM1 (smem, double-buffered, swizzled) -> logits write + gumbel ->
//   online softmax (flash rescale) -> p into smem (aliases Bs buf0) ->
//   GEMM2 accumulate zq in registers (book from L1/L2, coalesced).
// smem: As 16KB + Bs 64KB = 80KB dynamic -> 2 CTAs/SM.
// ---------------------------------------------------------------------------
#define TMR 16
#define NCH 512
#define KT  16

__global__ __launch_bounds__(256, 2) void fused_kernel(
    const float* __restrict__ book, const float* __restrict__ lpq,
    const void* __restrict__ temp_ptr, float* __restrict__ out)
{
    extern __shared__ float sm[];
    float* As = sm;                // [256][16]
    float* Bs = sm + 4096;         // [2][16][512] (swizzled cols)
    float* Pv = Bs;                // alias of buffer 0: [16][512] probs
    __shared__ float red[8][4];
    __shared__ float m_run[TMR], s_run[TMR], scale_s[TMR], zsq_s[TMR];

    int t = threadIdx.x;
    int lane = t & 31, warp = t >> 5;
    int rg = t >> 6;               // row group: rows rg*4 .. rg*4+3
    int cg = t & 63;               // col group: cols cg*8 .. cg*8+7 (GEMM1) / dims cg*4.. (GEMM2)
    int r0 = blockIdx.x * TMR;

    float tval;
    {
        float f = *reinterpret_cast<const float*>(temp_ptr);
        int  iv = *reinterpret_cast<const int*>(temp_ptr);
        tval = (f >= 0.015625f && f <= 64.0f) ? f : (float)iv;
    }
    float invT = 1.0f / tval;
    float prec = 0.5f / fmaxf(expf(lpq[0]), 1e-10f);

    // load A tile transposed: As[k][row]
    {
        int row = t & 15, k0 = (t >> 4) * 16;
        const float4* src = reinterpret_cast<const float4*>(g_zp + (size_t)(r0 + row) * DIM_ + k0);
#pragma unroll
        for (int j = 0; j < 4; j++) {
            float4 v = src[j];
            As[(k0 + j*4 + 0)*16 + row] = v.x;
            As[(k0 + j*4 + 1)*16 + row] = v.y;
            As[(k0 + j*4 + 2)*16 + row] = v.z;
            As[(k0 + j*4 + 3)*16 + row] = v.w;
        }
    }
    if (t < TMR) { m_run[t] = -3.4e38f; s_run[t] = 0.f; zsq_s[t] = g_zpsq[r0 + t]; }

    float accq[4][4];
#pragma unroll
    for (int i = 0; i < 4; i++)
#pragma unroll
        for (int d = 0; d < 4; d++) accq[i][d] = 0.f;

    for (int c = 0; c < 4; c++) {
        int c0 = c * NCH;
        __syncthreads();  // Pv/Bs free from previous chunk; As/zsq ready (first iter)

        // stage book tile s (16 k x 512 cols) into buffer buf, transposed+swizzled
        auto stage = [&](int s, int buf) {
#pragma unroll
            for (int rep = 0; rep < 8; rep++) {
                int fidx = rep * 256 + t;
                int col = fidx >> 2, j = fidx & 3;   // j = k-quad within tile
                float4 v = *reinterpret_cast<const float4*>(
                    &book[(size_t)(c0 + col) * DIM_ + s * KT + j * 4]);
                float* dst = Bs + buf * 8192 + (j * 4) * 512 + (col ^ (j << 2));
                dst[0] = v.x; dst[512] = v.y; dst[1024] = v.z; dst[1536] = v.w;
            }
        };
        stage(0, 0);
        __syncthreads();

        float acc1[4][8];
#pragma unroll
        for (int i = 0; i < 4; i++)
#pragma unroll
            for (int j = 0; j < 8; j++) acc1[i][j] = 0.f;

        for (int s = 0; s < 16; s++) {
            if (s < 15) stage(s + 1, (s + 1) & 1);
            const float* Bb = Bs + (s & 1) * 8192;
#pragma unroll
            for (int kk = 0; kk < KT; kk++) {
                float4 a = *reinterpret_cast<const float4*>(&As[(s * KT + kk) * 16 + rg * 4]);
                int sx = (kk >> 2) << 2;
                float4 b0 = *reinterpret_cast<const float4*>(&Bb[kk * 512 + ((cg * 8) ^ sx)]);
                float4 b1 = *reinterpret_cast<const float4*>(&Bb[kk * 512 + ((cg * 8 + 4) ^ sx)]);
                float av[4] = {a.x, a.y, a.z, a.w};
                float bv[8] = {b0.x, b0.y, b0.z, b0.w, b1.x, b1.y, b1.z, b1.w};
#pragma unroll
                for (int i = 0; i < 4; i++)
#pragma unroll
                    for (int j = 0; j < 8; j++)
                        acc1[i][j] = fmaf(av[i], bv[j], acc1[i][j]);
            }
            __syncthreads();
        }

        // epilogue: logits out, gumbel, v = (l+g)*invT kept in acc1; local max
        float vmax[4] = {-3.4e38f, -3.4e38f, -3.4e38f, -3.4e38f};
        float bqv[8];
#pragma unroll
        for (int j = 0; j < 8; j++) bqv[j] = g_booksq[c0 + cg * 8 + j];
#pragma unroll
        for (int i = 0; i < 4; i++) {
            int row = rg * 4 + i;
            float zr = zsq_s[row];
            size_t lbase = LOG_OFF + (size_t)(r0 + row) * BOOK_ + c0 + cg * 8;
            uint32_t ibase = (uint32_t)(r0 + row) * 2048u + (uint32_t)(c0 + cg * 8);
#pragma unroll
            for (int j = 0; j < 8; j++) {
                float l = -(zr + bqv[j] - 2.0f * acc1[i][j]) * prec;
                out[lbase + j] = l;
                uint32_t bits = threefry_bits_0_42(ibase + j);
                float u = __uint_as_float((bits >> 9) | 0x3f800000u) - 1.0f;
                float g = -__logf(-__logf(u + 1e-10f) + 1e-10f);
                float v = (l + g) * invT;
                acc1[i][j] = v;
                vmax[i] = fmaxf(vmax[i], v);
            }
        }
#pragma unroll
        for (int i = 0; i < 4; i++) {
            float m = vmax[i];
#pragma unroll
            for (int o = 16; o; o >>= 1) m = fmaxf(m, __shfl_xor_sync(0xffffffffu, m, o));
            if (lane == 0) red[warp][i] = m;
        }
        __syncthreads();
        if (t < TMR) {
            int rq = t >> 2, ii = t & 3;
            float mc = fmaxf(red[2 * rq][ii], red[2 * rq + 1][ii]);
            float mo = m_run[t], mn = fmaxf(mo, mc);
            scale_s[t] = __expf(mo - mn);   // first chunk: exp(-inf)=0
            m_run[t] = mn;
        }
        __syncthreads();

        // p = exp(v - m); write into Pv (aliases Bs buf0, now dead); partial sums
        float vs[4] = {0.f, 0.f, 0.f, 0.f};
#pragma unroll
        for (int i = 0; i < 4; i++) {
            int row = rg * 4 + i;
            float m = m_run[row];
            float4 p0, p1;
            p0.x = __expf(acc1[i][0] - m); p0.y = __expf(acc1[i][1] - m);
            p0.z = __expf(acc1[i][2] - m); p0.w = __expf(acc1[i][3] - m);
            p1.x = __expf(acc1[i][4] - m); p1.y = __expf(acc1[i][5] - m);
            p1.z = __expf(acc1[i][6] - m); p1.w = __expf(acc1[i][7] - m);
            vs[i] = ((p0.x + p0.y) + (p0.z + p0.w)) + ((p1.x + p1.y) + (p1.z + p1.w));
            *reinterpret_cast<float4*>(&Pv[row * 512 + cg * 8])     = p0;
            *reinterpret_cast<float4*>(&Pv[row * 512 + cg * 8 + 4]) = p1;
        }
#pragma unroll
        for (int i = 0; i < 4; i++) {
            float s = vs[i];
#pragma unroll
            for (int o = 16; o; o >>= 1) s += __shfl_xor_sync(0xffffffffu, s, o);
            if (lane == 0) red[warp][i] = s;
        }
        __syncthreads();
        if (t < TMR) {
            int rq = t >> 2, ii = t & 3;
            float sc = red[2 * rq][ii] + red[2 * rq + 1][ii];
            s_run[t] = s_run[t] * scale_s[t] + sc;
        }
        __syncthreads();

        // rescale running zq acc, then GEMM2 chunk: accq[i][dd] += p[row][col]*book[col][d]
#pragma unroll
        for (int i = 0; i < 4; i++) {
            float scl = scale_s[rg * 4 + i];
#pragma unroll
            for (int d = 0; d < 4; d++) accq[i][d] *= scl;
        }
        const float4* bp = reinterpret_cast<const float4*>(book) + (size_t)c0 * 64 + cg;
        for (int col = 0; col < NCH; col += 4) {
            float4 b0 = bp[(size_t)(col + 0) * 64];
            float4 b1 = bp[(size_t)(col + 1) * 64];
            float4 b2 = bp[(size_t)(col + 2) * 64];
            float4 b3 = bp[(size_t)(col + 3) * 64];
            float bb[4][4] = {{b0.x, b0.y, b0.z, b0.w}, {b1.x, b1.y, b1.z, b1.w},
                              {b2.x, b2.y, b2.z, b2.w}, {b3.x, b3.y, b3.z, b3.w}};
#pragma unroll
            for (int i = 0; i < 4; i++) {
                float4 p = *reinterpret_cast<const float4*>(&Pv[(rg * 4 + i) * 512 + col]);
                float pp[4] = {p.x, p.y, p.z, p.w};
#pragma unroll
                for (int cc = 0; cc < 4; cc++)
#pragma unroll
                    for (int dd = 0; dd < 4; dd++)
                        accq[i][dd] = fmaf(pp[cc], bb[cc][dd], accq[i][dd]);
            }
        }
    }

    // final: zq = accq / s_run
#pragma unroll
    for (int i = 0; i < 4; i++) {
        int row = rg * 4 + i;
        float is = 1.0f / s_run[row];
        float4 o;
        o.x = accq[i][0] * is; o.y = accq[i][1] * is;
        o.z = accq[i][2] * is; o.w = accq[i][3] * is;
        *reinterpret_cast<float4*>(&out[ZQ_OFF + (size_t)(r0 + row) * DIM_ + cg * 4]) = o;
    }
}

// ---------------------------------------------------------------------------
extern "C" void kernel_launch(void* const* d_in, const int* in_sizes, int n_in,
                              void* d_out, int out_size)
{
    const float* z       = (const float*)d_in[0];
    const float* c_probs = (const float*)d_in[1];
    const float* lpq     = (const float*)d_in[2];
    const float* book    = (const float*)d_in[3];
    const float* mu      = (const float*)d_in[4];
    const void*  temp    = d_in[5];
    float* out = (float*)d_out;

    cudaFuncSetAttribute(fused_kernel,
                         cudaFuncAttributeMaxDynamicSharedMemorySize, 81920);

    prep_kernel<<<ROWS_, 64>>>(z, c_probs, mu, out);
    booksq_kernel<<<BOOK_, 64>>>(book, lpq, out);
    fused_kernel<<<ROWS_ / TMR, 256, 81920>>>(book, lpq, temp, out);
}

// round 8
// speedup vs baseline: 1.8259x; 1.5943x over previous
#include <cuda_runtime.h>
#include <cstdint>
#include <math.h>

// Problem constants
#define B_     64
#define NPTS_  1024
#define DIM_   256
#define BOOK_  2048
#define NC_    16
#define ROWS_  65536

// Output layout: concat(zq, precision_q, logits, mu_mix)
#define ZQ_OFF   ((size_t)0)
#define PREC_OFF ((size_t)16777216)
#define LOG_OFF  ((size_t)16777217)
#define MU_OFF   ((size_t)150994945)

// Scratch
__device__ float g_zp[(size_t)ROWS_ * DIM_];     // 64 MB
__device__ float g_vbuf[(size_t)ROWS_ * BOOK_];  // 512 MB
__device__ float g_zpsq[ROWS_];
__device__ float g_booksq[BOOK_];

// ---------------------------------------------------------------------------
// Kernel 1: mu_mix = c_probs @ mu ; zp = z + mu_mix ; row norms
// ---------------------------------------------------------------------------
__global__ __launch_bounds__(64) void prep_kernel(
    const float* __restrict__ z, const float* __restrict__ c_probs,
    const float* __restrict__ mu, float* __restrict__ out)
{
    __shared__ float cp[NC_];
    __shared__ float red[2];
    int r = blockIdx.x;
    int b = r >> 10, n = r & 1023;
    int t = threadIdx.x;
    if (t < NC_) cp[t] = c_probs[b * NC_ + t];
    __syncthreads();

    const float4* z4 = reinterpret_cast<const float4*>(z) + (size_t)r * 64;
    float4 zv = z4[t];
    float4 m = make_float4(0.f, 0.f, 0.f, 0.f);
#pragma unroll
    for (int c = 0; c < NC_; c++) {
        const float4* mu4 = reinterpret_cast<const float4*>(mu) + ((size_t)c * NPTS_ + n) * 64;
        float4 mv = mu4[t];
        float w = cp[c];
        m.x = fmaf(w, mv.x, m.x); m.y = fmaf(w, mv.y, m.y);
        m.z = fmaf(w, mv.z, m.z); m.w = fmaf(w, mv.w, m.w);
    }
    float* om = out + MU_OFF + (size_t)r * DIM_ + t * 4;
    om[0] = m.x; om[1] = m.y; om[2] = m.z; om[3] = m.w;

    float4 zp = make_float4(zv.x + m.x, zv.y + m.y, zv.z + m.z, zv.w + m.w);
    reinterpret_cast<float4*>(g_zp)[(size_t)r * 64 + t] = zp;

    float ss = zp.x*zp.x + zp.y*zp.y + zp.z*zp.z + zp.w*zp.w;
#pragma unroll
    for (int o = 16; o; o >>= 1) ss += __shfl_xor_sync(0xffffffffu, ss, o);
    if ((t & 31) == 0) red[t >> 5] = ss;
    __syncthreads();
    if (t == 0) g_zpsq[r] = red[0] + red[1];
}

// ---------------------------------------------------------------------------
// Kernel 2: book norms + precision_q
// ---------------------------------------------------------------------------
__global__ __launch_bounds__(64) void booksq_kernel(
    const float* __restrict__ book, const float* __restrict__ lpq,
    float* __restrict__ out)
{
    __shared__ float red[2];
    int r = blockIdx.x, t = threadIdx.x;
    float4 v = reinterpret_cast<const float4*>(book)[(size_t)r * 64 + t];
    float ss = v.x*v.x + v.y*v.y + v.z*v.z + v.w*v.w;
#pragma unroll
    for (int o = 16; o; o >>= 1) ss += __shfl_xor_sync(0xffffffffu, ss, o);
    if ((t & 31) == 0) red[t >> 5] = ss;
    __syncthreads();
    if (t == 0) g_booksq[r] = red[0] + red[1];
    if (r == 0 && t == 0) out[PREC_OFF] = 0.5f / fmaxf(expf(lpq[0]), 1e-10f);
}

// ---------------------------------------------------------------------------
// helpers: tf32 split + mma.sync (sm_80+ PTX, compiles for compute_103)
// ---------------------------------------------------------------------------
__device__ __forceinline__ void split2(float x, uint32_t& hi, uint32_t& lo) {
    uint32_t h;
    asm("cvt.rna.tf32.f32 %0, %1;" : "=r"(h) : "f"(x));
    float l = x - __uint_as_float(h);
    uint32_t lw;
    asm("cvt.rna.tf32.f32 %0, %1;" : "=r"(lw) : "f"(l));
    hi = h; lo = lw;
}
__device__ __forceinline__ void mma8(float* d, uint32_t a0, uint32_t a1, uint32_t a2, uint32_t a3,
                                     uint32_t b0, uint32_t b1) {
    asm volatile("mma.sync.aligned.m16n8k8.row.col.f32.tf32.tf32.f32 "
        "{%0,%1,%2,%3}, {%4,%5,%6,%7}, {%8,%9}, {%0,%1,%2,%3};"
        : "+f"(d[0]), "+f"(d[1]), "+f"(d[2]), "+f"(d[3])
        : "r"(a0), "r"(a1), "r"(a2), "r"(a3), "r"(b0), "r"(b1));
}

// JAX threefry2x32-20, key (0,42), partitionable: bits = x0 ^ x1
__device__ __forceinline__ uint32_t threefry_bits_0_42(uint32_t idx)
{
    const uint32_t ks1 = 42u, ks2 = 0x1BD11BDAu ^ 42u;
    uint32_t x0 = 0u, x1 = idx + ks1;
#define TFR(r) { x0 += x1; x1 = (x1 << (r)) | (x1 >> (32 - (r))); x1 ^= x0; }
    TFR(13) TFR(15) TFR(26) TFR(6)
    x0 += ks1; x1 += ks2 + 1u;
    TFR(17) TFR(29) TFR(16) TFR(24)
    x0 += ks2; x1 += 2u;
    TFR(13) TFR(15) TFR(26) TFR(6)
    x1 += ks1 + 3u;
    TFR(17) TFR(29) TFR(16) TFR(24)
    x0 += ks1; x1 += ks2 + 4u;
    TFR(13) TFR(15) TFR(26) TFR(6)
    x0 += ks2; x1 += 5u;
#undef TFR
    return x0 ^ x1;
}

// ---------------------------------------------------------------------------
// Fused kernel: 64 rows/CTA, 256 thr, 16 chunks of 128 cols.
// Phase1: GEMM1 (3xTF32 mma) -> logits + gumbel -> vbuf + rowmax.
// Phase2: p = exp(v-max) -> GEMM2 (3xTF32 mma) -> zq.
// ---------------------------------------------------------------------------
#define PVP 132
#define ASP 36
#define B1P 137
#define B2P 264
#define SMEM_DYN ((64*PVP + 32*B2P) * 4)

__global__ __launch_bounds__(256) void fused_kernel(
    const float* __restrict__ book, const float* __restrict__ lpq,
    const void* __restrict__ temp_ptr, float* __restrict__ out)
{
    extern __shared__ float sm[];
    float* Pv  = sm;                  // [64][132]
    float* St  = sm + 64 * PVP;       // stage union (8448 floats)
    float* As  = St;                  // [64][36]
    float* Bs1 = St + 64 * ASP;       // [32][137]
    float* Bs2 = St;                  // [32][264]
    __shared__ float m_s[64], s_s[64], zsq_s[64], bq_s[128];

    int t = threadIdx.x, lane = t & 31, w = t >> 5;
    int wm = w & 3, wn = w >> 2;
    int lr = lane >> 2, lc = lane & 3;
    int r0 = blockIdx.x * 64;

    float tval;
    {
        float f = *reinterpret_cast<const float*>(temp_ptr);
        int iv = *reinterpret_cast<const int*>(temp_ptr);
        tval = (f >= 0.015625f && f <= 64.0f) ? f : (float)iv;
    }
    float invT = 1.0f / tval;
    float prec = 0.5f / fmaxf(expf(lpq[0]), 1e-10f);

    if (t < 64) { m_s[t] = -3.4e38f; s_s[t] = 0.f; zsq_s[t] = g_zpsq[r0 + t]; }

    // ============================ PHASE 1 ============================
    for (int c = 0; c < 16; c++) {
        int c0 = c * 128;
        __syncthreads();                       // Pv free, bq_s writable
        if (t < 128) bq_s[t] = g_booksq[c0 + t];

        float acc1[8][4];
#pragma unroll
        for (int i = 0; i < 8; i++)
#pragma unroll
            for (int j = 0; j < 4; j++) acc1[i][j] = 0.f;

        for (int kb = 0; kb < 8; kb++) {
            __syncthreads();
            // stage A [64m x 32k]
#pragma unroll
            for (int i = 0; i < 2; i++) {
                int f = i * 256 + t, m = f >> 3, kq = f & 7;
                float4 v = *(const float4*)&g_zp[(size_t)(r0 + m) * DIM_ + kb * 32 + kq * 4];
                *(float4*)&As[m * ASP + kq * 4] = v;
            }
            // stage B1 [32k x 128n] transposed
#pragma unroll
            for (int i = 0; i < 4; i++) {
                int f = i * 256 + t, n = f >> 3, kq = f & 7;
                float4 v = *(const float4*)&book[(size_t)(c0 + n) * DIM_ + kb * 32 + kq * 4];
                Bs1[(kq * 4 + 0) * B1P + n] = v.x;
                Bs1[(kq * 4 + 1) * B1P + n] = v.y;
                Bs1[(kq * 4 + 2) * B1P + n] = v.z;
                Bs1[(kq * 4 + 3) * B1P + n] = v.w;
            }
            __syncthreads();
#pragma unroll
            for (int s = 0; s < 4; s++) {
                int kA = s * 8 + lc;
                float af0 = As[(wm * 16 + lr) * ASP + kA];
                float af1 = As[(wm * 16 + lr + 8) * ASP + kA];
                float af2 = As[(wm * 16 + lr) * ASP + kA + 4];
                float af3 = As[(wm * 16 + lr + 8) * ASP + kA + 4];
                uint32_t ah[4], al[4];
                split2(af0, ah[0], al[0]); split2(af1, ah[1], al[1]);
                split2(af2, ah[2], al[2]); split2(af3, ah[3], al[3]);
#pragma unroll
                for (int tl = 0; tl < 8; tl++) {
                    int nB = wn * 64 + tl * 8 + lr;
                    float bf0 = Bs1[kA * B1P + nB];
                    float bf1 = Bs1[(kA + 4) * B1P + nB];
                    uint32_t bh0, bl0, bh1, bl1;
                    split2(bf0, bh0, bl0); split2(bf1, bh1, bl1);
                    mma8(acc1[tl], ah[0], ah[1], ah[2], ah[3], bh0, bh1);
                    mma8(acc1[tl], ah[0], ah[1], ah[2], ah[3], bl0, bl1);
                    mma8(acc1[tl], al[0], al[1], al[2], al[3], bh0, bh1);
                }
            }
        }
        // fragments -> logits in Pv
        __syncthreads();
#pragma unroll
        for (int tl = 0; tl < 8; tl++) {
#pragma unroll
            for (int i2 = 0; i2 < 4; i2++) {
                int row = wm * 16 + lr + ((i2 >> 1) << 3);
                int col = wn * 64 + tl * 8 + lc * 2 + (i2 & 1);
                Pv[row * PVP + col] = -(zsq_s[row] + bq_s[col] - 2.0f * acc1[tl][i2]) * prec;
            }
        }
        __syncthreads();
        // coalesced logits store (streaming)
        {
            const float* lg = Pv;
#pragma unroll 4
            for (int i = 0; i < 32; i++) {
                int f = i * 256 + t, row = f >> 7, col = f & 127;
                float lv = lg[row * PVP + col];
                __stcs(&out[LOG_OFF + (size_t)(r0 + row) * BOOK_ + c0 + col], lv);
            }
        }
        // gumbel + v -> vbuf, rowmax
        for (int i = 0; i < 8; i++) {
            int row = i * 8 + w;
            float4 l4 = *(float4*)&Pv[row * PVP + lane * 4];
            uint32_t ib = (uint32_t)(r0 + row) * 2048u + (uint32_t)(c0 + lane * 4);
            float v[4] = {l4.x, l4.y, l4.z, l4.w};
#pragma unroll
            for (int j = 0; j < 4; j++) {
                uint32_t bits = threefry_bits_0_42(ib + j);
                float u = __uint_as_float((bits >> 9) | 0x3f800000u) - 1.0f;
                float g = -__logf(-__logf(u + 1e-10f) + 1e-10f);
                v[j] = (v[j] + g) * invT;
            }
            float4 v4 = make_float4(v[0], v[1], v[2], v[3]);
            *(float4*)&g_vbuf[(size_t)(r0 + row) * BOOK_ + c0 + lane * 4] = v4;
            float mx = fmaxf(fmaxf(v[0], v[1]), fmaxf(v[2], v[3]));
#pragma unroll
            for (int o = 16; o; o >>= 1) mx = fmaxf(mx, __shfl_xor_sync(0xffffffffu, mx, o));
            if (lane == 0) m_s[row] = fmaxf(m_s[row], mx);
        }
    }

    // ============================ PHASE 2 ============================
    float acc2[16][4];
#pragma unroll
    for (int i = 0; i < 16; i++)
#pragma unroll
        for (int j = 0; j < 4; j++) acc2[i][j] = 0.f;

    for (int c = 0; c < 16; c++) {
        int c0 = c * 128;
        __syncthreads();                       // Pv free
        for (int i = 0; i < 8; i++) {
            int row = i * 8 + w;
            float4 v4 = *(const float4*)&g_vbuf[(size_t)(r0 + row) * BOOK_ + c0 + lane * 4];
            float m = m_s[row];
            float4 p4;
            p4.x = __expf(v4.x - m); p4.y = __expf(v4.y - m);
            p4.z = __expf(v4.z - m); p4.w = __expf(v4.w - m);
            *(float4*)&Pv[row * PVP + lane * 4] = p4;
            float sp = (p4.x + p4.y) + (p4.z + p4.w);
#pragma unroll
            for (int o = 16; o; o >>= 1) sp += __shfl_xor_sync(0xffffffffu, sp, o);
            if (lane == 0) s_s[row] += sp;
        }
        for (int kb = 0; kb < 4; kb++) {
            __syncthreads();
            // stage B2 [32k x 256n] = book rows (c0+kb*32 ..)
#pragma unroll
            for (int i = 0; i < 8; i++) {
                int f = i * 256 + t, kRow = f >> 6, n4 = f & 63;
                float4 v = *(const float4*)&book[(size_t)(c0 + kb * 32 + kRow) * DIM_ + n4 * 4];
                *(float4*)&Bs2[kRow * B2P + n4 * 4] = v;
            }
            __syncthreads();
#pragma unroll
            for (int s = 0; s < 4; s++) {
                int kA = kb * 32 + s * 8 + lc;
                float af0 = Pv[(wm * 16 + lr) * PVP + kA];
                float af1 = Pv[(wm * 16 + lr + 8) * PVP + kA];
                float af2 = Pv[(wm * 16 + lr) * PVP + kA + 4];
                float af3 = Pv[(wm * 16 + lr + 8) * PVP + kA + 4];
                uint32_t ah[4], al[4];
                split2(af0, ah[0], al[0]); split2(af1, ah[1], al[1]);
                split2(af2, ah[2], al[2]); split2(af3, ah[3], al[3]);
                int kB = s * 8 + lc;
#pragma unroll
                for (int tl = 0; tl < 16; tl++) {
                    int nB = wn * 128 + tl * 8 + lr;
                    float bf0 = Bs2[kB * B2P + nB];
                    float bf1 = Bs2[(kB + 4) * B2P + nB];
                    uint32_t bh0, bl0, bh1, bl1;
                    split2(bf0, bh0, bl0); split2(bf1, bh1, bl1);
                    mma8(acc2[tl], ah[0], ah[1], ah[2], ah[3], bh0, bh1);
                    mma8(acc2[tl], ah[0], ah[1], ah[2], ah[3], bl0, bl1);
                    mma8(acc2[tl], al[0], al[1], al[2], al[3], bh0, bh1);
                }
            }
        }
    }
    __syncthreads();
    {
        int rowA = wm * 16 + lr;
        float s0 = 1.0f / s_s[rowA];
        float s1 = 1.0f / s_s[rowA + 8];
#pragma unroll
        for (int tl = 0; tl < 16; tl++) {
            int col = wn * 128 + tl * 8 + lc * 2;
            float2 v01 = make_float2(acc2[tl][0] * s0, acc2[tl][1] * s0);
            *(float2*)&out[ZQ_OFF + (size_t)(r0 + rowA) * DIM_ + col] = v01;
            float2 v23 = make_float2(acc2[tl][2] * s1, acc2[tl][3] * s1);
            *(float2*)&out[ZQ_OFF + (size_t)(r0 + rowA + 8) * DIM_ + col] = v23;
        }
    }
}

// ---------------------------------------------------------------------------
extern "C" void kernel_launch(void* const* d_in, const int* in_sizes, int n_in,
                              void* d_out, int out_size)
{
    const float* z       = (const float*)d_in[0];
    const float* c_probs = (const float*)d_in[1];
    const float* lpq     = (const float*)d_in[2];
    const float* book    = (const float*)d_in[3];
    const float* mu      = (const float*)d_in[4];
    const void*  temp    = d_in[5];
    float* out = (float*)d_out;

    cudaFuncSetAttribute(fused_kernel, cudaFuncAttributeMaxDynamicSharedMemorySize, SMEM_DYN);

    prep_kernel<<<ROWS_, 64>>>(z, c_probs, mu, out);
    booksq_kernel<<<BOOK_, 64>>>(book, lpq, out);
    fused_kernel<<<ROWS_ / 64, 256, SMEM_DYN>>>(book, lpq, temp, out);
}

// round 9
// speedup vs baseline: 1.8345x; 1.0047x over previous
#include <cuda_runtime.h>
#include <cstdint>
#include <math.h>

// Problem constants
#define B_     64
#define NPTS_  1024
#define DIM_   256
#define BOOK_  2048
#define NC_    16
#define ROWS_  65536

// Output layout: concat(zq, precision_q, logits, mu_mix)
#define ZQ_OFF   ((size_t)0)
#define PREC_OFF ((size_t)16777216)
#define LOG_OFF  ((size_t)16777217)
#define MU_OFF   ((size_t)150994945)

// Scratch
__device__ float g_zp[(size_t)ROWS_ * DIM_];       // 64 MB fp32 zp
__device__ float g_book_hi[(size_t)BOOK_ * DIM_];  // 2 MB tf32-hi
__device__ float g_book_lo[(size_t)BOOK_ * DIM_];  // 2 MB tf32-lo
__device__ float g_zpsq[ROWS_];
__device__ float g_booksq[BOOK_];

// ---------------------------------------------------------------------------
// Kernel 1: mu_mix = c_probs @ mu ; zp = z + mu_mix ; row norms
// ---------------------------------------------------------------------------
__global__ __launch_bounds__(64) void prep_kernel(
    const float* __restrict__ z, const float* __restrict__ c_probs,
    const float* __restrict__ mu, float* __restrict__ out)
{
    __shared__ float cp[NC_];
    __shared__ float red[2];
    int r = blockIdx.x;
    int b = r >> 10, n = r & 1023;
    int t = threadIdx.x;
    if (t < NC_) cp[t] = c_probs[b * NC_ + t];
    __syncthreads();

    const float4* z4 = reinterpret_cast<const float4*>(z) + (size_t)r * 64;
    float4 zv = z4[t];
    float4 m = make_float4(0.f, 0.f, 0.f, 0.f);
#pragma unroll
    for (int c = 0; c < NC_; c++) {
        const float4* mu4 = reinterpret_cast<const float4*>(mu) + ((size_t)c * NPTS_ + n) * 64;
        float4 mv = mu4[t];
        float w = cp[c];
        m.x = fmaf(w, mv.x, m.x); m.y = fmaf(w, mv.y, m.y);
        m.z = fmaf(w, mv.z, m.z); m.w = fmaf(w, mv.w, m.w);
    }
    float* om = out + MU_OFF + (size_t)r * DIM_ + t * 4;
    om[0] = m.x; om[1] = m.y; om[2] = m.z; om[3] = m.w;

    float4 zp = make_float4(zv.x + m.x, zv.y + m.y, zv.z + m.z, zv.w + m.w);
    reinterpret_cast<float4*>(g_zp)[(size_t)r * 64 + t] = zp;

    float ss = zp.x*zp.x + zp.y*zp.y + zp.z*zp.z + zp.w*zp.w;
#pragma unroll
    for (int o = 16; o; o >>= 1) ss += __shfl_xor_sync(0xffffffffu, ss, o);
    if ((t & 31) == 0) red[t >> 5] = ss;
    __syncthreads();
    if (t == 0) g_zpsq[r] = red[0] + red[1];
}

// ---------------------------------------------------------------------------
// Kernel 2: book norms + precision_q + tf32 hi/lo split of book
// ---------------------------------------------------------------------------
__global__ __launch_bounds__(64) void book_prep_kernel(
    const float* __restrict__ book, const float* __restrict__ lpq,
    float* __restrict__ out)
{
    __shared__ float red[2];
    int r = blockIdx.x, t = threadIdx.x;
    float4 v = reinterpret_cast<const float4*>(book)[(size_t)r * 64 + t];
    float4 hi, lo;
    uint32_t h;
    asm("cvt.rna.tf32.f32 %0, %1;" : "=r"(h) : "f"(v.x)); hi.x = __uint_as_float(h);
    asm("cvt.rna.tf32.f32 %0, %1;" : "=r"(h) : "f"(v.y)); hi.y = __uint_as_float(h);
    asm("cvt.rna.tf32.f32 %0, %1;" : "=r"(h) : "f"(v.z)); hi.z = __uint_as_float(h);
    asm("cvt.rna.tf32.f32 %0, %1;" : "=r"(h) : "f"(v.w)); hi.w = __uint_as_float(h);
    asm("cvt.rna.tf32.f32 %0, %1;" : "=r"(h) : "f"(v.x - hi.x)); lo.x = __uint_as_float(h);
    asm("cvt.rna.tf32.f32 %0, %1;" : "=r"(h) : "f"(v.y - hi.y)); lo.y = __uint_as_float(h);
    asm("cvt.rna.tf32.f32 %0, %1;" : "=r"(h) : "f"(v.z - hi.z)); lo.z = __uint_as_float(h);
    asm("cvt.rna.tf32.f32 %0, %1;" : "=r"(h) : "f"(v.w - hi.w)); lo.w = __uint_as_float(h);
    reinterpret_cast<float4*>(g_book_hi)[(size_t)r * 64 + t] = hi;
    reinterpret_cast<float4*>(g_book_lo)[(size_t)r * 64 + t] = lo;

    float ss = v.x*v.x + v.y*v.y + v.z*v.z + v.w*v.w;
#pragma unroll
    for (int o = 16; o; o >>= 1) ss += __shfl_xor_sync(0xffffffffu, ss, o);
    if ((t & 31) == 0) red[t >> 5] = ss;
    __syncthreads();
    if (t == 0) g_booksq[r] = red[0] + red[1];
    if (r == 0 && t == 0) out[PREC_OFF] = 0.5f / fmaxf(expf(lpq[0]), 1e-10f);
}

// ---------------------------------------------------------------------------
// helpers
// ---------------------------------------------------------------------------
__device__ __forceinline__ void split2(float x, uint32_t& hi, uint32_t& lo) {
    uint32_t h;
    asm("cvt.rna.tf32.f32 %0, %1;" : "=r"(h) : "f"(x));
    float l = x - __uint_as_float(h);
    uint32_t lw;
    asm("cvt.rna.tf32.f32 %0, %1;" : "=r"(lw) : "f"(l));
    hi = h; lo = lw;
}
__device__ __forceinline__ void mma8(float* d, uint32_t a0, uint32_t a1, uint32_t a2, uint32_t a3,
                                     uint32_t b0, uint32_t b1) {
    asm volatile("mma.sync.aligned.m16n8k8.row.col.f32.tf32.tf32.f32 "
        "{%0,%1,%2,%3}, {%4,%5,%6,%7}, {%8,%9}, {%0,%1,%2,%3};"
        : "+f"(d[0]), "+f"(d[1]), "+f"(d[2]), "+f"(d[3])
        : "r"(a0), "r"(a1), "r"(a2), "r"(a3), "r"(b0), "r"(b1));
}

// JAX threefry2x32-20, key (0,42), partitionable: bits = x0 ^ x1
__device__ __forceinline__ uint32_t threefry_bits_0_42(uint32_t idx)
{
    const uint32_t ks1 = 42u, ks2 = 0x1BD11BDAu ^ 42u;
    uint32_t x0 = 0u, x1 = idx + ks1;
#define TFR(r) { x0 += x1; x1 = (x1 << (r)) | (x1 >> (32 - (r))); x1 ^= x0; }
    TFR(13) TFR(15) TFR(26) TFR(6)
    x0 += ks1; x1 += ks2 + 1u;
    TFR(17) TFR(29) TFR(16) TFR(24)
    x0 += ks2; x1 += 2u;
    TFR(13) TFR(15) TFR(26) TFR(6)
    x1 += ks1 + 3u;
    TFR(17) TFR(29) TFR(16) TFR(24)
    x0 += ks1; x1 += ks2 + 4u;
    TFR(13) TFR(15) TFR(26) TFR(6)
    x0 += ks2; x1 += 5u;
#undef TFR
    return x0 ^ x1;
}

// ---------------------------------------------------------------------------
// Fused kernel: 64 rows/CTA, 256 thr, 16 chunks of 128 cols, online softmax.
// Per chunk: GEMM1 (3xTF32, book pre-split) -> logits store + gumbel ->
// online max/scale -> p in smem -> rescale acc2 -> GEMM2 chunk.
// ---------------------------------------------------------------------------
#define PVP 132
#define ASP 36
#define B1P 137
#define B2P 264
// union: max(As + 2*Bs1, 2*Bs2) = max(2304+8768, 16896) = 16896 floats
#define SMEM_DYN ((64*PVP + 16896) * 4)

__global__ __launch_bounds__(256, 2) void fused_kernel(
    const float* __restrict__ book, const float* __restrict__ lpq,
    const void* __restrict__ temp_ptr, float* __restrict__ out)
{
    extern __shared__ float sm[];
    float* Pv   = sm;                      // [64][132] logits -> v -> p
    float* St   = sm + 64 * PVP;           // stage union
    float* As   = St;                      // [64][36] fp32 A tile
    float* Bs1h = St + 64 * ASP;           // [32][137]
    float* Bs1l = Bs1h + 32 * B1P;         // [32][137]
    float* Bs2h = St;                      // [32][264]
    float* Bs2l = St + 32 * B2P;           // [32][264]
    __shared__ float m_s[64], s_s[64], scale_s[64], zsq_s[64], bq_s[128];

    int t = threadIdx.x, lane = t & 31, w = t >> 5;
    int wm = w & 3, wn = w >> 2;
    int lr = lane >> 2, lc = lane & 3;
    int r0 = blockIdx.x * 64;

    float tval;
    {
        float f = *reinterpret_cast<const float*>(temp_ptr);
        int iv = *reinterpret_cast<const int*>(temp_ptr);
        tval = (f >= 0.015625f && f <= 64.0f) ? f : (float)iv;
    }
    float invT = 1.0f / tval;
    float prec = 0.5f / fmaxf(expf(lpq[0]), 1e-10f);

    if (t < 64) { m_s[t] = -3.4e38f; s_s[t] = 0.f; zsq_s[t] = g_zpsq[r0 + t]; }

    float acc2[16][4];
#pragma unroll
    for (int i = 0; i < 16; i++)
#pragma unroll
        for (int j = 0; j < 4; j++) acc2[i][j] = 0.f;

    for (int c = 0; c < 16; c++) {
        int c0 = c * 128;
        __syncthreads();                   // Pv + St free, bq_s writable
        if (t < 128) bq_s[t] = g_booksq[c0 + t];

        // ---------------- GEMM1: acc1 = zp-chunk @ book-chunk^T ----------------
        float acc1[8][4];
#pragma unroll
        for (int i = 0; i < 8; i++)
#pragma unroll
            for (int j = 0; j < 4; j++) acc1[i][j] = 0.f;

        for (int kb = 0; kb < 8; kb++) {
            __syncthreads();
            // stage A fp32 [64m x 32k]
#pragma unroll
            for (int i = 0; i < 2; i++) {
                int f = i * 256 + t, m = f >> 3, kq = f & 7;
                float4 v = *(const float4*)&g_zp[(size_t)(r0 + m) * DIM_ + kb * 32 + kq * 4];
                *(float4*)&As[m * ASP + kq * 4] = v;
            }
            // stage B1 hi/lo [32k x 128n] transposed (pre-split book)
#pragma unroll
            for (int i = 0; i < 4; i++) {
                int f = i * 256 + t, n = f >> 3, kq = f & 7;
                size_t src = (size_t)(c0 + n) * DIM_ + kb * 32 + kq * 4;
                float4 vh = *(const float4*)&g_book_hi[src];
                float4 vl = *(const float4*)&g_book_lo[src];
                Bs1h[(kq * 4 + 0) * B1P + n] = vh.x; Bs1l[(kq * 4 + 0) * B1P + n] = vl.x;
                Bs1h[(kq * 4 + 1) * B1P + n] = vh.y; Bs1l[(kq * 4 + 1) * B1P + n] = vl.y;
                Bs1h[(kq * 4 + 2) * B1P + n] = vh.z; Bs1l[(kq * 4 + 2) * B1P + n] = vl.z;
                Bs1h[(kq * 4 + 3) * B1P + n] = vh.w; Bs1l[(kq * 4 + 3) * B1P + n] = vl.w;
            }
            __syncthreads();
#pragma unroll
            for (int s = 0; s < 4; s++) {
                int kA = s * 8 + lc;
                uint32_t ah[4], al[4];
                split2(As[(wm * 16 + lr) * ASP + kA],     ah[0], al[0]);
                split2(As[(wm * 16 + lr + 8) * ASP + kA], ah[1], al[1]);
                split2(As[(wm * 16 + lr) * ASP + kA + 4],     ah[2], al[2]);
                split2(As[(wm * 16 + lr + 8) * ASP + kA + 4], ah[3], al[3]);
#pragma unroll
                for (int tl = 0; tl < 8; tl++) {
                    int nB = wn * 64 + tl * 8 + lr;
                    uint32_t bh0 = __float_as_uint(Bs1h[kA * B1P + nB]);
                    uint32_t bh1 = __float_as_uint(Bs1h[(kA + 4) * B1P + nB]);
                    uint32_t bl0 = __float_as_uint(Bs1l[kA * B1P + nB]);
                    uint32_t bl1 = __float_as_uint(Bs1l[(kA + 4) * B1P + nB]);
                    mma8(acc1[tl], ah[0], ah[1], ah[2], ah[3], bh0, bh1);
                    mma8(acc1[tl], ah[0], ah[1], ah[2], ah[3], bl0, bl1);
                    mma8(acc1[tl], al[0], al[1], al[2], al[3], bh0, bh1);
                }
            }
        }
        // fragments -> logits in Pv (rows are per-warp exclusive)
#pragma unroll
        for (int tl = 0; tl < 8; tl++) {
#pragma unroll
            for (int i2 = 0; i2 < 4; i2++) {
                int row = wm * 16 + lr + ((i2 >> 1) << 3);
                int col = wn * 64 + tl * 8 + lc * 2 + (i2 & 1);
                Pv[row * PVP + col] = -(zsq_s[row] + bq_s[col] - 2.0f * acc1[tl][i2]) * prec;
            }
        }
        __syncthreads();
        // coalesced streaming logits store
#pragma unroll 4
        for (int i = 0; i < 32; i++) {
            int f = i * 256 + t, row = f >> 7, col = f & 127;
            __stcs(&out[LOG_OFF + (size_t)(r0 + row) * BOOK_ + c0 + col], Pv[row * PVP + col]);
        }
        // gumbel + online softmax update; p -> Pv
        for (int i = 0; i < 8; i++) {
            int row = i * 8 + w;
            float4 l4 = *(float4*)&Pv[row * PVP + lane * 4];
            uint32_t ib = (uint32_t)(r0 + row) * 2048u + (uint32_t)(c0 + lane * 4);
            float v[4] = {l4.x, l4.y, l4.z, l4.w};
#pragma unroll
            for (int j = 0; j < 4; j++) {
                uint32_t bits = threefry_bits_0_42(ib + j);
                float u = __uint_as_float((bits >> 9) | 0x3f800000u) - 1.0f;
                float g = -__logf(-__logf(u + 1e-10f) + 1e-10f);
                v[j] = (v[j] + g) * invT;
            }
            float mc = fmaxf(fmaxf(v[0], v[1]), fmaxf(v[2], v[3]));
#pragma unroll
            for (int o = 16; o; o >>= 1) mc = fmaxf(mc, __shfl_xor_sync(0xffffffffu, mc, o));
            float m_old = m_s[row];
            float m_new = fmaxf(m_old, mc);
            float scl = __expf(m_old - m_new);
            float4 p4;
            p4.x = __expf(v[0] - m_new); p4.y = __expf(v[1] - m_new);
            p4.z = __expf(v[2] - m_new); p4.w = __expf(v[3] - m_new);
            *(float4*)&Pv[row * PVP + lane * 4] = p4;
            float sp = (p4.x + p4.y) + (p4.z + p4.w);
#pragma unroll
            for (int o = 16; o; o >>= 1) sp += __shfl_xor_sync(0xffffffffu, sp, o);
            if (lane == 0) {
                s_s[row] = s_s[row] * scl + sp;
                m_s[row] = m_new;
                scale_s[row] = scl;
            }
        }
        __syncthreads();                   // p + scale_s ready; St free for Bs2

        // rescale running zq accumulators
        {
            int rowA = wm * 16 + lr;
            float s0 = scale_s[rowA], s1 = scale_s[rowA + 8];
#pragma unroll
            for (int tl = 0; tl < 16; tl++) {
                acc2[tl][0] *= s0; acc2[tl][1] *= s0;
                acc2[tl][2] *= s1; acc2[tl][3] *= s1;
            }
        }

        // ---------------- GEMM2: acc2 += p-chunk @ book-chunk ----------------
        for (int kb = 0; kb < 4; kb++) {
            __syncthreads();
            // stage B2 hi/lo [32k x 256n] (pre-split book rows)
#pragma unroll
            for (int i = 0; i < 8; i++) {
                int f = i * 256 + t, kRow = f >> 6, n4 = f & 63;
                size_t src = (size_t)(c0 + kb * 32 + kRow) * DIM_ + n4 * 4;
                *(float4*)&Bs2h[kRow * B2P + n4 * 4] = *(const float4*)&g_book_hi[src];
                *(float4*)&Bs2l[kRow * B2P + n4 * 4] = *(const float4*)&g_book_lo[src];
            }
            __syncthreads();
#pragma unroll
            for (int s = 0; s < 4; s++) {
                int kA = kb * 32 + s * 8 + lc;
                uint32_t ah[4], al[4];
                split2(Pv[(wm * 16 + lr) * PVP + kA],     ah[0], al[0]);
                split2(Pv[(wm * 16 + lr + 8) * PVP + kA], ah[1], al[1]);
                split2(Pv[(wm * 16 + lr) * PVP + kA + 4],     ah[2], al[2]);
                split2(Pv[(wm * 16 + lr + 8) * PVP + kA + 4], ah[3], al[3]);
                int kB = s * 8 + lc;
#pragma unroll
                for (int tl = 0; tl < 16; tl++) {
                    int nB = wn * 128 + tl * 8 + lr;
                    uint32_t bh0 = __float_as_uint(Bs2h[kB * B2P + nB]);
                    uint32_t bh1 = __float_as_uint(Bs2h[(kB + 4) * B2P + nB]);
                    uint32_t bl0 = __float_as_uint(Bs2l[kB * B2P + nB]);
                    uint32_t bl1 = __float_as_uint(Bs2l[(kB + 4) * B2P + nB]);
                    mma8(acc2[tl], ah[0], ah[1], ah[2], ah[3], bh0, bh1);
                    mma8(acc2[tl], ah[0], ah[1], ah[2], ah[3], bl0, bl1);
                    mma8(acc2[tl], al[0], al[1], al[2], al[3], bh0, bh1);
                }
            }
        }
    }

    __syncthreads();
    {
        int rowA = wm * 16 + lr;
        float s0 = 1.0f / s_s[rowA];
        float s1 = 1.0f / s_s[rowA + 8];
#pragma unroll
        for (int tl = 0; tl < 16; tl++) {
            int col = wn * 128 + tl * 8 + lc * 2;
            float2 v01 = make_float2(acc2[tl][0] * s0, acc2[tl][1] * s0);
            *(float2*)&out[ZQ_OFF + (size_t)(r0 + rowA) * DIM_ + col] = v01;
            float2 v23 = make_float2(acc2[tl][2] * s1, acc2[tl][3] * s1);
            *(float2*)&out[ZQ_OFF + (size_t)(r0 + rowA + 8) * DIM_ + col] = v23;
        }
    }
}

// ---------------------------------------------------------------------------
extern "C" void kernel_launch(void* const* d_in, const int* in_sizes, int n_in,
                              void* d_out, int out_size)
{
    const float* z       = (const float*)d_in[0];
    const float* c_probs = (const float*)d_in[1];
    const float* lpq     = (const float*)d_in[2];
    const float* book    = (const float*)d_in[3];
    const float* mu      = (const float*)d_in[4];
    const void*  temp    = d_in[5];
    float* out = (float*)d_out;

    cudaFuncSetAttribute(fused_kernel, cudaFuncAttributeMaxDynamicSharedMemorySize, SMEM_DYN);

    prep_kernel<<<ROWS_, 64>>>(z, c_probs, mu, out);
    book_prep_kernel<<<BOOK_, 64>>>(book, lpq, out);
    fused_kernel<<<ROWS_ / 64, 256, SMEM_DYN>>>(book, lpq, temp, out);
}

// round 10
// speedup vs baseline: 1.8990x; 1.0352x over previous
#include <cuda_runtime.h>
#include <cstdint>
#include <math.h>

// Problem constants
#define B_     64
#define NPTS_  1024
#define DIM_   256
#define BOOK_  2048
#define NC_    16
#define ROWS_  65536

// Output layout: concat(zq, precision_q, logits, mu_mix)
#define ZQ_OFF   ((size_t)0)
#define PREC_OFF ((size_t)16777216)
#define LOG_OFF  ((size_t)16777217)
#define MU_OFF   ((size_t)150994945)

// Scratch
__device__ float g_zp[(size_t)ROWS_ * DIM_];       // 64 MB fp32 zp
__device__ float g_book_hi[(size_t)BOOK_ * DIM_];  // 2 MB tf32-hi
__device__ float g_book_lo[(size_t)BOOK_ * DIM_];  // 2 MB tf32-lo
__device__ float g_vbuf[(size_t)ROWS_ * BOOK_];    // 512 MB (l+g)/T
__device__ float g_zpsq[ROWS_];
__device__ float g_booksq[BOOK_];
__device__ float g_rowmax[ROWS_];

// ---------------------------------------------------------------------------
// Kernel 1: mu_mix = c_probs @ mu ; zp = z + mu_mix ; row norms
// ---------------------------------------------------------------------------
__global__ __launch_bounds__(64) void prep_kernel(
    const float* __restrict__ z, const float* __restrict__ c_probs,
    const float* __restrict__ mu, float* __restrict__ out)
{
    __shared__ float cp[NC_];
    __shared__ float red[2];
    int r = blockIdx.x;
    int b = r >> 10, n = r & 1023;
    int t = threadIdx.x;
    if (t < NC_) cp[t] = c_probs[b * NC_ + t];
    __syncthreads();

    const float4* z4 = reinterpret_cast<const float4*>(z) + (size_t)r * 64;
    float4 zv = z4[t];
    float4 m = make_float4(0.f, 0.f, 0.f, 0.f);
#pragma unroll
    for (int c = 0; c < NC_; c++) {
        const float4* mu4 = reinterpret_cast<const float4*>(mu) + ((size_t)c * NPTS_ + n) * 64;
        float4 mv = mu4[t];
        float w = cp[c];
        m.x = fmaf(w, mv.x, m.x); m.y = fmaf(w, mv.y, m.y);
        m.z = fmaf(w, mv.z, m.z); m.w = fmaf(w, mv.w, m.w);
    }
    float* om = out + MU_OFF + (size_t)r * DIM_ + t * 4;
    om[0] = m.x; om[1] = m.y; om[2] = m.z; om[3] = m.w;

    float4 zp = make_float4(zv.x + m.x, zv.y + m.y, zv.z + m.z, zv.w + m.w);
    reinterpret_cast<float4*>(g_zp)[(size_t)r * 64 + t] = zp;

    float ss = zp.x*zp.x + zp.y*zp.y + zp.z*zp.z + zp.w*zp.w;
#pragma unroll
    for (int o = 16; o; o >>= 1) ss += __shfl_xor_sync(0xffffffffu, ss, o);
    if ((t & 31) == 0) red[t >> 5] = ss;
    __syncthreads();
    if (t == 0) g_zpsq[r] = red[0] + red[1];
}

// ---------------------------------------------------------------------------
// Kernel 2: book norms + precision_q + tf32 hi/lo split of book
// ---------------------------------------------------------------------------
__global__ __launch_bounds__(64) void book_prep_kernel(
    const float* __restrict__ book, const float* __restrict__ lpq,
    float* __restrict__ out)
{
    __shared__ float red[2];
    int r = blockIdx.x, t = threadIdx.x;
    float4 v = reinterpret_cast<const float4*>(book)[(size_t)r * 64 + t];
    float4 hi, lo;
    uint32_t h;
    asm("cvt.rna.tf32.f32 %0, %1;" : "=r"(h) : "f"(v.x)); hi.x = __uint_as_float(h);
    asm("cvt.rna.tf32.f32 %0, %1;" : "=r"(h) : "f"(v.y)); hi.y = __uint_as_float(h);
    asm("cvt.rna.tf32.f32 %0, %1;" : "=r"(h) : "f"(v.z)); hi.z = __uint_as_float(h);
    asm("cvt.rna.tf32.f32 %0, %1;" : "=r"(h) : "f"(v.w)); hi.w = __uint_as_float(h);
    asm("cvt.rna.tf32.f32 %0, %1;" : "=r"(h) : "f"(v.x - hi.x)); lo.x = __uint_as_float(h);
    asm("cvt.rna.tf32.f32 %0, %1;" : "=r"(h) : "f"(v.y - hi.y)); lo.y = __uint_as_float(h);
    asm("cvt.rna.tf32.f32 %0, %1;" : "=r"(h) : "f"(v.z - hi.z)); lo.z = __uint_as_float(h);
    asm("cvt.rna.tf32.f32 %0, %1;" : "=r"(h) : "f"(v.w - hi.w)); lo.w = __uint_as_float(h);
    reinterpret_cast<float4*>(g_book_hi)[(size_t)r * 64 + t] = hi;
    reinterpret_cast<float4*>(g_book_lo)[(size_t)r * 64 + t] = lo;

    float ss = v.x*v.x + v.y*v.y + v.z*v.z + v.w*v.w;
#pragma unroll
    for (int o = 16; o; o >>= 1) ss += __shfl_xor_sync(0xffffffffu, ss, o);
    if ((t & 31) == 0) red[t >> 5] = ss;
    __syncthreads();
    if (t == 0) g_booksq[r] = red[0] + red[1];
    if (r == 0 && t == 0) out[PREC_OFF] = 0.5f / fmaxf(expf(lpq[0]), 1e-10f);
}

// ---------------------------------------------------------------------------
// helpers
// ---------------------------------------------------------------------------
__device__ __forceinline__ void split2(float x, uint32_t& hi, uint32_t& lo) {
    uint32_t h;
    asm("cvt.rna.tf32.f32 %0, %1;" : "=r"(h) : "f"(x));
    float l = x - __uint_as_float(h);
    uint32_t lw;
    asm("cvt.rna.tf32.f32 %0, %1;" : "=r"(lw) : "f"(l));
    hi = h; lo = lw;
}
__device__ __forceinline__ void mma8(float* d, uint32_t a0, uint32_t a1, uint32_t a2, uint32_t a3,
                                     uint32_t b0, uint32_t b1) {
    asm volatile("mma.sync.aligned.m16n8k8.row.col.f32.tf32.tf32.f32 "
        "{%0,%1,%2,%3}, {%4,%5,%6,%7}, {%8,%9}, {%0,%1,%2,%3};"
        : "+f"(d[0]), "+f"(d[1]), "+f"(d[2]), "+f"(d[3])
        : "r"(a0), "r"(a1), "r"(a2), "r"(a3), "r"(b0), "r"(b1));
}

// JAX threefry2x32-20, key (0,42), partitionable: bits = x0 ^ x1
__device__ __forceinline__ uint32_t threefry_bits_0_42(uint32_t idx)
{
    const uint32_t ks1 = 42u, ks2 = 0x1BD11BDAu ^ 42u;
    uint32_t x0 = 0u, x1 = idx + ks1;
#define TFR(r) { x0 += x1; x1 = (x1 << (r)) | (x1 >> (32 - (r))); x1 ^= x0; }
    TFR(13) TFR(15) TFR(26) TFR(6)
    x0 += ks1; x1 += ks2 + 1u;
    TFR(17) TFR(29) TFR(16) TFR(24)
    x0 += ks2; x1 += 2u;
    TFR(13) TFR(15) TFR(26) TFR(6)
    x1 += ks1 + 3u;
    TFR(17) TFR(29) TFR(16) TFR(24)
    x0 += ks1; x1 += ks2 + 4u;
    TFR(13) TFR(15) TFR(26) TFR(6)
    x0 += ks2; x1 += 5u;
#undef TFR
    return x0 ^ x1;
}

#define PVP 132
#define ASP 36
#define B1P 137
#define B2P 264

// ---------------------------------------------------------------------------
// Kernel A: GEMM1 (3xTF32) -> logits store -> gumbel -> v to vbuf + rowmax
// 64 rows/CTA, 256 thr, 16 chunks of 128 cols. Low reg pressure (acc1 only).
// ---------------------------------------------------------------------------
#define SMEM_A ((64*PVP + 64*ASP + 2*32*B1P) * 4)

__global__ __launch_bounds__(256, 2) void g1_kernel(
    const float* __restrict__ lpq, const void* __restrict__ temp_ptr,
    float* __restrict__ out)
{
    extern __shared__ float sm[];
    float* Pv   = sm;                      // [64][132] logits staging
    float* As   = sm + 64 * PVP;           // [64][36]
    float* Bs1h = As + 64 * ASP;           // [32][137]
    float* Bs1l = Bs1h + 32 * B1P;         // [32][137]
    __shared__ float zsq_s[64], bq_s[128];

    int t = threadIdx.x, lane = t & 31, w = t >> 5;
    int wm = w & 3, wn = w >> 2;
    int lr = lane >> 2, lc = lane & 3;
    int r0 = blockIdx.x * 64;

    float tval;
    {
        float f = *reinterpret_cast<const float*>(temp_ptr);
        int iv = *reinterpret_cast<const int*>(temp_ptr);
        tval = (f >= 0.015625f && f <= 64.0f) ? f : (float)iv;
    }
    float invT = 1.0f / tval;
    float prec = 0.5f / fmaxf(expf(lpq[0]), 1e-10f);

    if (t < 64) zsq_s[t] = g_zpsq[r0 + t];

    float rmax[8];
#pragma unroll
    for (int i = 0; i < 8; i++) rmax[i] = -3.4e38f;

    for (int c = 0; c < 16; c++) {
        int c0 = c * 128;
        __syncthreads();
        if (t < 128) bq_s[t] = g_booksq[c0 + t];

        float acc1[8][4];
#pragma unroll
        for (int i = 0; i < 8; i++)
#pragma unroll
            for (int j = 0; j < 4; j++) acc1[i][j] = 0.f;

        for (int kb = 0; kb < 8; kb++) {
            __syncthreads();
#pragma unroll
            for (int i = 0; i < 2; i++) {
                int f = i * 256 + t, m = f >> 3, kq = f & 7;
                float4 v = *(const float4*)&g_zp[(size_t)(r0 + m) * DIM_ + kb * 32 + kq * 4];
                *(float4*)&As[m * ASP + kq * 4] = v;
            }
#pragma unroll
            for (int i = 0; i < 4; i++) {
                int f = i * 256 + t, n = f >> 3, kq = f & 7;
                size_t src = (size_t)(c0 + n) * DIM_ + kb * 32 + kq * 4;
                float4 vh = *(const float4*)&g_book_hi[src];
                float4 vl = *(const float4*)&g_book_lo[src];
                Bs1h[(kq * 4 + 0) * B1P + n] = vh.x; Bs1l[(kq * 4 + 0) * B1P + n] = vl.x;
                Bs1h[(kq * 4 + 1) * B1P + n] = vh.y; Bs1l[(kq * 4 + 1) * B1P + n] = vl.y;
                Bs1h[(kq * 4 + 2) * B1P + n] = vh.z; Bs1l[(kq * 4 + 2) * B1P + n] = vl.z;
                Bs1h[(kq * 4 + 3) * B1P + n] = vh.w; Bs1l[(kq * 4 + 3) * B1P + n] = vl.w;
            }
            __syncthreads();
#pragma unroll
            for (int s = 0; s < 4; s++) {
                int kA = s * 8 + lc;
                uint32_t ah[4], al[4];
                split2(As[(wm * 16 + lr) * ASP + kA],     ah[0], al[0]);
                split2(As[(wm * 16 + lr + 8) * ASP + kA], ah[1], al[1]);
                split2(As[(wm * 16 + lr) * ASP + kA + 4],     ah[2], al[2]);
                split2(As[(wm * 16 + lr + 8) * ASP + kA + 4], ah[3], al[3]);
#pragma unroll
                for (int tl = 0; tl < 8; tl++) {
                    int nB = wn * 64 + tl * 8 + lr;
                    uint32_t bh0 = __float_as_uint(Bs1h[kA * B1P + nB]);
                    uint32_t bh1 = __float_as_uint(Bs1h[(kA + 4) * B1P + nB]);
                    uint32_t bl0 = __float_as_uint(Bs1l[kA * B1P + nB]);
                    uint32_t bl1 = __float_as_uint(Bs1l[(kA + 4) * B1P + nB]);
                    mma8(acc1[tl], ah[0], ah[1], ah[2], ah[3], bh0, bh1);
                    mma8(acc1[tl], ah[0], ah[1], ah[2], ah[3], bl0, bl1);
                    mma8(acc1[tl], al[0], al[1], al[2], al[3], bh0, bh1);
                }
            }
        }
        // fragments -> logits in Pv
#pragma unroll
        for (int tl = 0; tl < 8; tl++) {
#pragma unroll
            for (int i2 = 0; i2 < 4; i2++) {
                int row = wm * 16 + lr + ((i2 >> 1) << 3);
                int col = wn * 64 + tl * 8 + lc * 2 + (i2 & 1);
                Pv[row * PVP + col] = -(zsq_s[row] + bq_s[col] - 2.0f * acc1[tl][i2]) * prec;
            }
        }
        __syncthreads();
        // coalesced streaming logits store (odd offset -> scalar)
#pragma unroll 4
        for (int i = 0; i < 32; i++) {
            int f = i * 256 + t, row = f >> 7, col = f & 127;
            __stcs(&out[LOG_OFF + (size_t)(r0 + row) * BOOK_ + c0 + col], Pv[row * PVP + col]);
        }
        // gumbel -> v -> vbuf; per-warp-row register max
#pragma unroll
        for (int i = 0; i < 8; i++) {
            int row = i * 8 + w;
            float4 l4 = *(float4*)&Pv[row * PVP + lane * 4];
            uint32_t ib = (uint32_t)(r0 + row) * 2048u + (uint32_t)(c0 + lane * 4);
            float v[4] = {l4.x, l4.y, l4.z, l4.w};
#pragma unroll
            for (int j = 0; j < 4; j++) {
                uint32_t bits = threefry_bits_0_42(ib + j);
                float u = __uint_as_float((bits >> 9) | 0x3f800000u) - 1.0f;
                float g = -__logf(-__logf(u + 1e-10f) + 1e-10f);
                v[j] = (v[j] + g) * invT;
            }
            float4 v4 = make_float4(v[0], v[1], v[2], v[3]);
            __stcs((float4*)&g_vbuf[(size_t)(r0 + row) * BOOK_ + c0 + lane * 4], v4);
            rmax[i] = fmaxf(rmax[i], fmaxf(fmaxf(v[0], v[1]), fmaxf(v[2], v[3])));
        }
    }
    // final rowmax reduce + store (each row owned by one warp)
#pragma unroll
    for (int i = 0; i < 8; i++) {
        float m = rmax[i];
#pragma unroll
        for (int o = 16; o; o >>= 1) m = fmaxf(m, __shfl_xor_sync(0xffffffffu, m, o));
        if (lane == 0) g_rowmax[r0 + i * 8 + w] = m;
    }
}

// ---------------------------------------------------------------------------
// Kernel B: p = exp(v - max) -> GEMM2 (3xTF32) -> zq = acc / sum
// 64 rows/CTA, 256 thr. acc2 (64 regs) is the only big register state.
// ---------------------------------------------------------------------------
#define SMEM_B ((64*PVP + 2*32*B2P) * 4)

__global__ __launch_bounds__(256, 2) void g2_kernel(float* __restrict__ out)
{
    extern __shared__ float sm[];
    float* Pv   = sm;                      // [64][132] p
    float* Bs2h = sm + 64 * PVP;           // [32][264]
    float* Bs2l = Bs2h + 32 * B2P;         // [32][264]
    __shared__ float s_s[64];

    int t = threadIdx.x, lane = t & 31, w = t >> 5;
    int wm = w & 3, wn = w >> 2;
    int lr = lane >> 2, lc = lane & 3;
    int r0 = blockIdx.x * 64;

    float mrow[8], ssum[8];
#pragma unroll
    for (int i = 0; i < 8; i++) {
        mrow[i] = g_rowmax[r0 + i * 8 + w];
        ssum[i] = 0.f;
    }

    float acc2[16][4];
#pragma unroll
    for (int i = 0; i < 16; i++)
#pragma unroll
        for (int j = 0; j < 4; j++) acc2[i][j] = 0.f;

    for (int c = 0; c < 16; c++) {
        int c0 = c * 128;
        __syncthreads();                   // Pv free
#pragma unroll
        for (int i = 0; i < 8; i++) {
            int row = i * 8 + w;
            float4 v4 = __ldcs((const float4*)&g_vbuf[(size_t)(r0 + row) * BOOK_ + c0 + lane * 4]);
            float4 p4;
            p4.x = __expf(v4.x - mrow[i]); p4.y = __expf(v4.y - mrow[i]);
            p4.z = __expf(v4.z - mrow[i]); p4.w = __expf(v4.w - mrow[i]);
            *(float4*)&Pv[row * PVP + lane * 4] = p4;
            ssum[i] += (p4.x + p4.y) + (p4.z + p4.w);
        }
        for (int kb = 0; kb < 4; kb++) {
            __syncthreads();
#pragma unroll
            for (int i = 0; i < 8; i++) {
                int f = i * 256 + t, kRow = f >> 6, n4 = f & 63;
                size_t src = (size_t)(c0 + kb * 32 + kRow) * DIM_ + n4 * 4;
                *(float4*)&Bs2h[kRow * B2P + n4 * 4] = *(const float4*)&g_book_hi[src];
                *(float4*)&Bs2l[kRow * B2P + n4 * 4] = *(const float4*)&g_book_lo[src];
            }
            __syncthreads();
#pragma unroll
            for (int s = 0; s < 4; s++) {
                int kA = kb * 32 + s * 8 + lc;
                uint32_t ah[4], al[4];
                split2(Pv[(wm * 16 + lr) * PVP + kA],     ah[0], al[0]);
                split2(Pv[(wm * 16 + lr + 8) * PVP + kA], ah[1], al[1]);
                split2(Pv[(wm * 16 + lr) * PVP + kA + 4],     ah[2], al[2]);
                split2(Pv[(wm * 16 + lr + 8) * PVP + kA + 4], ah[3], al[3]);
                int kB = s * 8 + lc;
#pragma unroll
                for (int tl = 0; tl < 16; tl++) {
                    int nB = wn * 128 + tl * 8 + lr;
                    uint32_t bh0 = __float_as_uint(Bs2h[kB * B2P + nB]);
                    uint32_t bh1 = __float_as_uint(Bs2h[(kB + 4) * B2P + nB]);
                    uint32_t bl0 = __float_as_uint(Bs2l[kB * B2P + nB]);
                    uint32_t bl1 = __float_as_uint(Bs2l[(kB + 4) * B2P + nB]);
                    mma8(acc2[tl], ah[0], ah[1], ah[2], ah[3], bh0, bh1);
                    mma8(acc2[tl], ah[0], ah[1], ah[2], ah[3], bl0, bl1);
                    mma8(acc2[tl], al[0], al[1], al[2], al[3], bh0, bh1);
                }
            }
        }
    }

    // row sums -> smem
#pragma unroll
    for (int i = 0; i < 8; i++) {
        float s = ssum[i];
#pragma unroll
        for (int o = 16; o; o >>= 1) s += __shfl_xor_sync(0xffffffffu, s, o);
        if (lane == 0) s_s[i * 8 + w] = s;
    }
    __syncthreads();
    {
        int rowA = wm * 16 + lr;
        float s0 = 1.0f / s_s[rowA];
        float s1 = 1.0f / s_s[rowA + 8];
#pragma unroll
        for (int tl = 0; tl < 16; tl++) {
            int col = wn * 128 + tl * 8 + lc * 2;
            float2 v01 = make_float2(acc2[tl][0] * s0, acc2[tl][1] * s0);
            *(float2*)&out[ZQ_OFF + (size_t)(r0 + rowA) * DIM_ + col] = v01;
            float2 v23 = make_float2(acc2[tl][2] * s1, acc2[tl][3] * s1);
            *(float2*)&out[ZQ_OFF + (size_t)(r0 + rowA + 8) * DIM_ + col] = v23;
        }
    }
}

// ---------------------------------------------------------------------------
extern "C" void kernel_launch(void* const* d_in, const int* in_sizes, int n_in,
                              void* d_out, int out_size)
{
    const float* z       = (const float*)d_in[0];
    const float* c_probs = (const float*)d_in[1];
    const float* lpq     = (const float*)d_in[2];
    const float* book    = (const float*)d_in[3];
    const float* mu      = (const float*)d_in[4];
    const void*  temp    = d_in[5];
    float* out = (float*)d_out;

    cudaFuncSetAttribute(g1_kernel, cudaFuncAttributeMaxDynamicSharedMemorySize, SMEM_A);
    cudaFuncSetAttribute(g2_kernel, cudaFuncAttributeMaxDynamicSharedMemorySize, SMEM_B);

    prep_kernel<<<ROWS_, 64>>>(z, c_probs, mu, out);
    book_prep_kernel<<<BOOK_, 64>>>(book, lpq, out);
    g1_kernel<<<ROWS_ / 64, 256, SMEM_A>>>(lpq, temp, out);
    g2_kernel<<<ROWS_ / 64, 256, SMEM_B>>>(out);
}

// round 12
// speedup vs baseline: 2.1354x; 1.1244x over previous
#include <cuda_runtime.h>
#include <cstdint>
#include <math.h>

// Problem constants
#define B_     64
#define NPTS_  1024
#define DIM_   256
#define BOOK_  2048
#define NC_    16
#define ROWS_  65536

// Output layout: concat(zq, precision_q, logits, mu_mix)
#define ZQ_OFF   ((size_t)0)
#define PREC_OFF ((size_t)16777216)
#define LOG_OFF  ((size_t)16777217)
#define MU_OFF   ((size_t)150994945)

// Scratch
__device__ float g_zp[(size_t)ROWS_ * DIM_];       // 64 MB fp32 zp
__device__ float g_book_hi[(size_t)BOOK_ * DIM_];  // 2 MB tf32-hi [col][d]
__device__ float g_book_lo[(size_t)BOOK_ * DIM_];
__device__ float g_bookT_hi[(size_t)DIM_ * BOOK_]; // 2 MB tf32-hi [d][col]
__device__ float g_bookT_lo[(size_t)DIM_ * BOOK_];
__device__ float4 g_pk1[262144];                   // 4 MB packed B for GEMM1
__device__ float4 g_pk2[262144];                   // 4 MB packed B for GEMM2
__device__ float g_vbuf[(size_t)ROWS_ * BOOK_];    // 512 MB (l+g)/T
__device__ float g_zpsq[ROWS_];
__device__ float g_booksq[BOOK_];
__device__ float g_rowmax[ROWS_];

// ---------------------------------------------------------------------------
// Kernel 1: mu_mix = c_probs @ mu ; zp = z + mu_mix ; row norms
// ---------------------------------------------------------------------------
__global__ __launch_bounds__(64) void prep_kernel(
    const float* __restrict__ z, const float* __restrict__ c_probs,
    const float* __restrict__ mu, float* __restrict__ out)
{
    __shared__ float cp[NC_];
    __shared__ float red[2];
    int r = blockIdx.x;
    int b = r >> 10, n = r & 1023;
    int t = threadIdx.x;
    if (t < NC_) cp[t] = c_probs[b * NC_ + t];
    __syncthreads();

    const float4* z4 = reinterpret_cast<const float4*>(z) + (size_t)r * 64;
    float4 zv = z4[t];
    float4 m = make_float4(0.f, 0.f, 0.f, 0.f);
#pragma unroll
    for (int c = 0; c < NC_; c++) {
        const float4* mu4 = reinterpret_cast<const float4*>(mu) + ((size_t)c * NPTS_ + n) * 64;
        float4 mv = mu4[t];
        float w = cp[c];
        m.x = fmaf(w, mv.x, m.x); m.y = fmaf(w, mv.y, m.y);
        m.z = fmaf(w, mv.z, m.z); m.w = fmaf(w, mv.w, m.w);
    }
    float* om = out + MU_OFF + (size_t)r * DIM_ + t * 4;
    om[0] = m.x; om[1] = m.y; om[2] = m.z; om[3] = m.w;

    float4 zp = make_float4(zv.x + m.x, zv.y + m.y, zv.z + m.z, zv.w + m.w);
    reinterpret_cast<float4*>(g_zp)[(size_t)r * 64 + t] = zp;

    float ss = zp.x*zp.x + zp.y*zp.y + zp.z*zp.z + zp.w*zp.w;
#pragma unroll
    for (int o = 16; o; o >>= 1) ss += __shfl_xor_sync(0xffffffffu, ss, o);
    if ((t & 31) == 0) red[t >> 5] = ss;
    __syncthreads();
    if (t == 0) g_zpsq[r] = red[0] + red[1];
}

// ---------------------------------------------------------------------------
// Kernel 2: book norms + precision_q + tf32 hi/lo split (row-major + transposed)
// ---------------------------------------------------------------------------
__global__ __launch_bounds__(64) void book_prep_kernel(
    const float* __restrict__ book, const float* __restrict__ lpq,
    float* __restrict__ out)
{
    __shared__ float red[2];
    int r = blockIdx.x, t = threadIdx.x;
    float4 v = reinterpret_cast<const float4*>(book)[(size_t)r * 64 + t];
    float4 hi, lo;
    uint32_t h;
    asm("cvt.rna.tf32.f32 %0, %1;" : "=r"(h) : "f"(v.x)); hi.x = __uint_as_float(h);
    asm("cvt.rna.tf32.f32 %0, %1;" : "=r"(h) : "f"(v.y)); hi.y = __uint_as_float(h);
    asm("cvt.rna.tf32.f32 %0, %1;" : "=r"(h) : "f"(v.z)); hi.z = __uint_as_float(h);
    asm("cvt.rna.tf32.f32 %0, %1;" : "=r"(h) : "f"(v.w)); hi.w = __uint_as_float(h);
    asm("cvt.rna.tf32.f32 %0, %1;" : "=r"(h) : "f"(v.x - hi.x)); lo.x = __uint_as_float(h);
    asm("cvt.rna.tf32.f32 %0, %1;" : "=r"(h) : "f"(v.y - hi.y)); lo.y = __uint_as_float(h);
    asm("cvt.rna.tf32.f32 %0, %1;" : "=r"(h) : "f"(v.z - hi.z)); lo.z = __uint_as_float(h);
    asm("cvt.rna.tf32.f32 %0, %1;" : "=r"(h) : "f"(v.w - hi.w)); lo.w = __uint_as_float(h);
    reinterpret_cast<float4*>(g_book_hi)[(size_t)r * 64 + t] = hi;
    reinterpret_cast<float4*>(g_book_lo)[(size_t)r * 64 + t] = lo;
    int d = t * 4;
    g_bookT_hi[(size_t)(d + 0) * BOOK_ + r] = hi.x;
    g_bookT_hi[(size_t)(d + 1) * BOOK_ + r] = hi.y;
    g_bookT_hi[(size_t)(d + 2) * BOOK_ + r] = hi.z;
    g_bookT_hi[(size_t)(d + 3) * BOOK_ + r] = hi.w;
    g_bookT_lo[(size_t)(d + 0) * BOOK_ + r] = lo.x;
    g_bookT_lo[(size_t)(d + 1) * BOOK_ + r] = lo.y;
    g_bookT_lo[(size_t)(d + 2) * BOOK_ + r] = lo.z;
    g_bookT_lo[(size_t)(d + 3) * BOOK_ + r] = lo.w;

    float ss = v.x*v.x + v.y*v.y + v.z*v.z + v.w*v.w;
#pragma unroll
    for (int o = 16; o; o >>= 1) ss += __shfl_xor_sync(0xffffffffu, ss, o);
    if ((t & 31) == 0) red[t >> 5] = ss;
    __syncthreads();
    if (t == 0) g_booksq[r] = red[0] + red[1];
    if (r == 0 && t == 0) out[PREC_OFF] = 0.5f / fmaxf(expf(lpq[0]), 1e-10f);
}

// ---------------------------------------------------------------------------
// Pack kernels: build B-fragment float4 tuples (hi[k],hi[k+4],lo[k],lo[k+4])
// pk1: B(k=dim, n=bookcol) per (chunk c, dim-block kb):
//   idx = ((c*8+kb)*16 + kidx)*128 + n; k0 = (kidx>>2)*8 + (kidx&3)
// pk2: B(k=bookcol, n=dim) per col-block cb:
//   idx = (cb*16 + kidx)*256 + n
// ---------------------------------------------------------------------------
__global__ __launch_bounds__(256) void pack1_kernel()
{
    int idx = blockIdx.x * 256 + threadIdx.x;
    int n = idx & 127;
    int kidx = (idx >> 7) & 15;
    int kbc = idx >> 11;            // c*8+kb, 0..127
    int k0 = ((kidx >> 2) << 3) + (kidx & 3);
    int d0 = (kbc & 7) * 32 + k0;
    int col = (kbc >> 3) * 128 + n;
    float h0 = g_bookT_hi[(size_t)d0 * BOOK_ + col];
    float h1 = g_bookT_hi[(size_t)(d0 + 4) * BOOK_ + col];
    float l0 = g_bookT_lo[(size_t)d0 * BOOK_ + col];
    float l1 = g_bookT_lo[(size_t)(d0 + 4) * BOOK_ + col];
    g_pk1[idx] = make_float4(h0, h1, l0, l1);
}

__global__ __launch_bounds__(256) void pack2_kernel()
{
    int idx = blockIdx.x * 256 + threadIdx.x;
    int n = idx & 255;
    int kidx = (idx >> 8) & 15;
    int cb = idx >> 12;             // 0..63
    int k0 = ((kidx >> 2) << 3) + (kidx & 3);
    int row0 = cb * 32 + k0;
    float h0 = g_book_hi[(size_t)row0 * DIM_ + n];
    float h1 = g_book_hi[(size_t)(row0 + 4) * DIM_ + n];
    float l0 = g_book_lo[(size_t)row0 * DIM_ + n];
    float l1 = g_book_lo[(size_t)(row0 + 4) * DIM_ + n];
    g_pk2[idx] = make_float4(h0, h1, l0, l1);
}

// ---------------------------------------------------------------------------
// helpers
// ---------------------------------------------------------------------------
__device__ __forceinline__ void split2(float x, uint32_t& hi, uint32_t& lo) {
    uint32_t h;
    asm("cvt.rna.tf32.f32 %0, %1;" : "=r"(h) : "f"(x));
    float l = x - __uint_as_float(h);
    uint32_t lw;
    asm("cvt.rna.tf32.f32 %0, %1;" : "=r"(lw) : "f"(l));
    hi = h; lo = lw;
}
__device__ __forceinline__ void mma8(float* d, const uint32_t* a, uint32_t b0, uint32_t b1) {
    asm volatile("mma.sync.aligned.m16n8k8.row.col.f32.tf32.tf32.f32 "
        "{%0,%1,%2,%3}, {%4,%5,%6,%7}, {%8,%9}, {%0,%1,%2,%3};"
        : "+f"(d[0]), "+f"(d[1]), "+f"(d[2]), "+f"(d[3])
        : "r"(a[0]), "r"(a[1]), "r"(a[2]), "r"(a[3]), "r"(b0), "r"(b1));
}

// JAX threefry2x32-20, key (0,42), partitionable: bits = x0 ^ x1
__device__ __forceinline__ uint32_t threefry_bits_0_42(uint32_t idx)
{
    const uint32_t ks1 = 42u, ks2 = 0x1BD11BDAu ^ 42u;
    uint32_t x0 = 0u, x1 = idx + ks1;
#define TFR(r) { x0 += x1; x1 = (x1 << (r)) | (x1 >> (32 - (r))); x1 ^= x0; }
    TFR(13) TFR(15) TFR(26) TFR(6)
    x0 += ks1; x1 += ks2 + 1u;
    TFR(17) TFR(29) TFR(16) TFR(24)
    x0 += ks2; x1 += 2u;
    TFR(13) TFR(15) TFR(26) TFR(6)
    x1 += ks1 + 3u;
    TFR(17) TFR(29) TFR(16) TFR(24)
    x0 += ks1; x1 += ks2 + 4u;
    TFR(13) TFR(15) TFR(26) TFR(6)
    x0 += ks2; x1 += 5u;
#undef TFR
    return x0 ^ x1;
}

#define PVP 132
#define ASP 36
#define PP1 130     // float4 pitch, ≡2 mod 8 -> conflict-free LDS.128
#define PP2 258

// ---------------------------------------------------------------------------
// Kernel A: GEMM1 (3xTF32, packed B) -> logits -> gumbel -> vbuf + rowmax
// ---------------------------------------------------------------------------
#define SMEM_A ((64*PVP + 64*ASP) * 4 + 16*PP1*16)

__global__ __launch_bounds__(256, 2) void g1_kernel(
    const float* __restrict__ lpq, const void* __restrict__ temp_ptr,
    float* __restrict__ out)
{
    extern __shared__ float sm[];
    float* Pv = sm;                              // [64][132]
    float* As = sm + 64 * PVP;                   // [64][36]
    float4* Pk = (float4*)(sm + 64 * PVP + 64 * ASP);  // [16][130] f4
    __shared__ float zsq_s[64], bq_s[128];

    int t = threadIdx.x, lane = t & 31, w = t >> 5;
    int wm = w & 3, wn = w >> 2;
    int lr = lane >> 2, lc = lane & 3;
    int r0 = blockIdx.x * 64;

    float tval;
    {
        float f = *reinterpret_cast<const float*>(temp_ptr);
        int iv = *reinterpret_cast<const int*>(temp_ptr);
        tval = (f >= 0.015625f && f <= 64.0f) ? f : (float)iv;
    }
    float invT = 1.0f / tval;
    float prec = 0.5f / fmaxf(expf(lpq[0]), 1e-10f);

    if (t < 64) zsq_s[t] = g_zpsq[r0 + t];

    float rmax[8];
#pragma unroll
    for (int i = 0; i < 8; i++) rmax[i] = -3.4e38f;

    for (int c = 0; c < 16; c++) {
        int c0 = c * 128;
        __syncthreads();
        if (t < 128) bq_s[t] = g_booksq[c0 + t];

        float acc1[8][4];
#pragma unroll
        for (int i = 0; i < 8; i++)
#pragma unroll
            for (int j = 0; j < 4; j++) acc1[i][j] = 0.f;

        for (int kb = 0; kb < 8; kb++) {
            __syncthreads();
            // stage A fp32 [64m x 32k]
#pragma unroll
            for (int i = 0; i < 2; i++) {
                int f = i * 256 + t, m = f >> 3, kq = f & 7;
                float4 v = *(const float4*)&g_zp[(size_t)(r0 + m) * DIM_ + kb * 32 + kq * 4];
                *(float4*)&As[m * ASP + kq * 4] = v;
            }
            // stage packed B: straight coalesced f4 copy
            {
                const float4* src = g_pk1 + (size_t)(c * 8 + kb) * 2048;
#pragma unroll
                for (int i = 0; i < 8; i++) {
                    int f = i * 256 + t;
                    Pk[(f >> 7) * PP1 + (f & 127)] = src[f];
                }
            }
            __syncthreads();
#pragma unroll
            for (int s = 0; s < 4; s++) {
                int kA = s * 8 + lc;
                uint32_t ah[4], al[4];
                split2(As[(wm * 16 + lr) * ASP + kA],     ah[0], al[0]);
                split2(As[(wm * 16 + lr + 8) * ASP + kA], ah[1], al[1]);
                split2(As[(wm * 16 + lr) * ASP + kA + 4],     ah[2], al[2]);
                split2(As[(wm * 16 + lr + 8) * ASP + kA + 4], ah[3], al[3]);
                const float4* prow = Pk + (s * 4 + lc) * PP1 + wn * 64 + lr;
#pragma unroll
                for (int tl = 0; tl < 8; tl++) {
                    float4 bv = prow[tl * 8];
                    uint32_t bh0 = __float_as_uint(bv.x), bh1 = __float_as_uint(bv.y);
                    uint32_t bl0 = __float_as_uint(bv.z), bl1 = __float_as_uint(bv.w);
                    mma8(acc1[tl], ah, bh0, bh1);
                    mma8(acc1[tl], ah, bl0, bl1);
                    mma8(acc1[tl], al, bh0, bh1);
                }
            }
        }
        // fragments -> logits in Pv
#pragma unroll
        for (int tl = 0; tl < 8; tl++) {
#pragma unroll
            for (int i2 = 0; i2 < 4; i2++) {
                int row = wm * 16 + lr + ((i2 >> 1) << 3);
                int col = wn * 64 + tl * 8 + lc * 2 + (i2 & 1);
                Pv[row * PVP + col] = -(zsq_s[row] + bq_s[col] - 2.0f * acc1[tl][i2]) * prec;
            }
        }
        __syncthreads();
        // coalesced streaming logits store (odd offset -> scalar)
#pragma unroll 4
        for (int i = 0; i < 32; i++) {
            int f = i * 256 + t, row = f >> 7, col = f & 127;
            __stcs(&out[LOG_OFF + (size_t)(r0 + row) * BOOK_ + c0 + col], Pv[row * PVP + col]);
        }
        // gumbel -> v -> vbuf; per-warp-row register max
#pragma unroll
        for (int i = 0; i < 8; i++) {
            int row = i * 8 + w;
            float4 l4 = *(float4*)&Pv[row * PVP + lane * 4];
            uint32_t ib = (uint32_t)(r0 + row) * 2048u + (uint32_t)(c0 + lane * 4);
            float v[4] = {l4.x, l4.y, l4.z, l4.w};
#pragma unroll
            for (int j = 0; j < 4; j++) {
                uint32_t bits = threefry_bits_0_42(ib + j);
                float u = __uint_as_float((bits >> 9) | 0x3f800000u) - 1.0f;
                float g = -__logf(-__logf(u + 1e-10f) + 1e-10f);
                v[j] = (v[j] + g) * invT;
            }
            float4 v4 = make_float4(v[0], v[1], v[2], v[3]);
            __stcs((float4*)&g_vbuf[(size_t)(r0 + row) * BOOK_ + c0 + lane * 4], v4);
            rmax[i] = fmaxf(rmax[i], fmaxf(fmaxf(v[0], v[1]), fmaxf(v[2], v[3])));
        }
    }
#pragma unroll
    for (int i = 0; i < 8; i++) {
        float m = rmax[i];
#pragma unroll
        for (int o = 16; o; o >>= 1) m = fmaxf(m, __shfl_xor_sync(0xffffffffu, m, o));
        if (lane == 0) g_rowmax[r0 + i * 8 + w] = m;
    }
}

// ---------------------------------------------------------------------------
// Kernel B: p = exp(v - max) -> GEMM2 (3xTF32, packed B) -> zq = acc / sum
// ---------------------------------------------------------------------------
#define SMEM_B ((64*PVP) * 4 + 16*PP2*16)

__global__ __launch_bounds__(256, 2) void g2_kernel(float* __restrict__ out)
{
    extern __shared__ float sm[];
    float* Pv = sm;                              // [64][132] p
    float4* Pk = (float4*)(sm + 64 * PVP);       // [16][258] f4
    __shared__ float s_s[64];

    int t = threadIdx.x, lane = t & 31, w = t >> 5;
    int wm = w & 3, wn = w >> 2;
    int lr = lane >> 2, lc = lane & 3;
    int r0 = blockIdx.x * 64;

    float mrow[8], ssum[8];
#pragma unroll
    for (int i = 0; i < 8; i++) {
        mrow[i] = g_rowmax[r0 + i * 8 + w];
        ssum[i] = 0.f;
    }

    float acc2[16][4];
#pragma unroll
    for (int i = 0; i < 16; i++)
#pragma unroll
        for (int j = 0; j < 4; j++) acc2[i][j] = 0.f;

    for (int c = 0; c < 16; c++) {
        int c0 = c * 128;
        __syncthreads();
#pragma unroll
        for (int i = 0; i < 8; i++) {
            int row = i * 8 + w;
            float4 v4 = __ldcs((const float4*)&g_vbuf[(size_t)(r0 + row) * BOOK_ + c0 + lane * 4]);
            float4 p4;
            p4.x = __expf(v4.x - mrow[i]); p4.y = __expf(v4.y - mrow[i]);
            p4.z = __expf(v4.z - mrow[i]); p4.w = __expf(v4.w - mrow[i]);
            *(float4*)&Pv[row * PVP + lane * 4] = p4;
            ssum[i] += (p4.x + p4.y) + (p4.z + p4.w);
        }
        for (int kb = 0; kb < 4; kb++) {
            __syncthreads();
            // stage packed B: straight coalesced f4 copy
            {
                const float4* src = g_pk2 + (size_t)(c * 4 + kb) * 4096;
#pragma unroll
                for (int i = 0; i < 16; i++) {
                    int f = i * 256 + t;
                    Pk[(f >> 8) * PP2 + (f & 255)] = src[f];
                }
            }
            __syncthreads();
#pragma unroll
            for (int s = 0; s < 4; s++) {
                int kA = kb * 32 + s * 8 + lc;
                uint32_t ah[4], al[4];
                split2(Pv[(wm * 16 + lr) * PVP + kA],     ah[0], al[0]);
                split2(Pv[(wm * 16 + lr + 8) * PVP + kA], ah[1], al[1]);
                split2(Pv[(wm * 16 + lr) * PVP + kA + 4],     ah[2], al[2]);
                split2(Pv[(wm * 16 + lr + 8) * PVP + kA + 4], ah[3], al[3]);
                const float4* prow = Pk + (s * 4 + lc) * PP2 + wn * 128 + lr;
#pragma unroll
                for (int tl = 0; tl < 16; tl++) {
                    float4 bv = prow[tl * 8];
                    uint32_t bh0 = __float_as_uint(bv.x), bh1 = __float_as_uint(bv.y);
                    uint32_t bl0 = __float_as_uint(bv.z), bl1 = __float_as_uint(bv.w);
                    mma8(acc2[tl], ah, bh0, bh1);
                    mma8(acc2[tl], ah, bl0, bl1);
                    mma8(acc2[tl], al, bh0, bh1);
                }
            }
        }
    }

#pragma unroll
    for (int i = 0; i < 8; i++) {
        float s = ssum[i];
#pragma unroll
        for (int o = 16; o; o >>= 1) s += __shfl_xor_sync(0xffffffffu, s, o);
        if (lane == 0) s_s[i * 8 + w] = s;
    }
    __syncthreads();
    {
        int rowA = wm * 16 + lr;
        float s0 = 1.0f / s_s[rowA];
        float s1 = 1.0f / s_s[rowA + 8];
#pragma unroll
        for (int tl = 0; tl < 16; tl++) {
            int col = wn * 128 + tl * 8 + lc * 2;
            float2 v01 = make_float2(acc2[tl][0] * s0, acc2[tl][1] * s0);
            *(float2*)&out[ZQ_OFF + (size_t)(r0 + rowA) * DIM_ + col] = v01;
            float2 v23 = make_float2(acc2[tl][2] * s1, acc2[tl][3] * s1);
            *(float2*)&out[ZQ_OFF + (size_t)(r0 + rowA + 8) * DIM_ + col] = v23;
        }
    }
}

// ---------------------------------------------------------------------------
extern "C" void kernel_launch(void* const* d_in, const int* in_sizes, int n_in,
                              void* d_out, int out_size)
{
    const float* z       = (const float*)d_in[0];
    const float* c_probs = (const float*)d_in[1];
    const float* lpq     = (const float*)d_in[2];
    const float* book    = (const float*)d_in[3];
    const float* mu      = (const float*)d_in[4];
    const void*  temp    = d_in[5];
    float* out = (float*)d_out;

    cudaFuncSetAttribute(g1_kernel, cudaFuncAttributeMaxDynamicSharedMemorySize, SMEM_A);
    cudaFuncSetAttribute(g2_kernel, cudaFuncAttributeMaxDynamicSharedMemorySize, SMEM_B);

    prep_kernel<<<ROWS_, 64>>>(z, c_probs, mu, out);
    book_prep_kernel<<<BOOK_, 64>>>(book, lpq, out);
    pack1_kernel<<<1024, 256>>>();
    pack2_kernel<<<1024, 256>>>();
    g1_kernel<<<ROWS_ / 64, 256, SMEM_A>>>(lpq, temp, out);
    g2_kernel<<<ROWS_ / 64, 256, SMEM_B>>>(out);
}